// round 1
// baseline (speedup 1.0000x reference)
#include <cuda_runtime.h>
#include <math.h>

// Problem constants
#define D_MODEL 768
#define NHEAD   12
#define DK      64
#define BATCH   2
#define SEQ     2048
#define MROWS   (BATCH*SEQ)   // 4096

// Scratch in device globals (allocation-free rule)
__device__ float g_q[MROWS * D_MODEL];
__device__ float g_k[MROWS * D_MODEL];
__device__ float g_v[MROWS * D_MODEL];
__device__ float g_ctx[MROWS * D_MODEL];
// Fallback attention buffer if d_out only holds `out`
__device__ float g_attn[(size_t)BATCH * NHEAD * SEQ * SEQ];

// ---------------------------------------------------------------------------
// Generic tiled fp32 GEMM: C = alpha * A * op(B) (+ bias)
// Tiles: BM=BN=64, BK=16, 16x16 threads, 4x4 register micro-tile.
// Batched over blockIdx.z with (z / ZH, z % ZH) offsets so the same kernel
// serves projections (z=0), per-(b,h) score GEMMs, and per-(b,h) PV GEMMs.
// All shapes here are multiples of the tile sizes, so no bounds checks.
// ---------------------------------------------------------------------------
#define BM 64
#define BN 64
#define BK 16

template <bool TRANS_B, bool HAS_BIAS>
__global__ void gemm_kernel(const float* __restrict__ A,
                            const float* __restrict__ B,
                            const float* __restrict__ bias,
                            float* __restrict__ C,
                            int K, int lda, int ldb, int ldc,
                            int zh,
                            long long sAb, long long sAh,
                            long long sBb, long long sBh,
                            long long sCb, long long sCh,
                            float alpha)
{
    const int z  = blockIdx.z;
    const int zb = z / zh;
    const int zr = z % zh;
    A += zb * sAb + zr * sAh;
    B += zb * sBb + zr * sBh;
    C += zb * sCb + zr * sCh;

    __shared__ float As[BK][BM];
    __shared__ float Bs[BK][BN];

    const int tx  = threadIdx.x;           // 0..15
    const int ty  = threadIdx.y;           // 0..15
    const int tid = ty * 16 + tx;          // 0..255
    const int m0  = blockIdx.y * BM;
    const int n0  = blockIdx.x * BN;

    float acc[4][4] = {};

    for (int k0 = 0; k0 < K; k0 += BK) {
        // Load A tile (64 rows x 16 k), float4 along k, store transposed
        {
            const int r  = tid >> 2;          // 0..63
            const int c4 = (tid & 3) * 4;     // 0,4,8,12
            const float4 v = *(const float4*)(A + (long long)(m0 + r) * lda + k0 + c4);
            As[c4 + 0][r] = v.x;
            As[c4 + 1][r] = v.y;
            As[c4 + 2][r] = v.z;
            As[c4 + 3][r] = v.w;
        }
        // Load B tile
        if (!TRANS_B) {
            // B is K x N row-major: rows k0..k0+15, cols n0..n0+63
            const int r  = tid >> 4;          // 0..15 (k)
            const int c4 = (tid & 15) * 4;    // 0..60 (n)
            const float4 v = *(const float4*)(B + (long long)(k0 + r) * ldb + n0 + c4);
            Bs[r][c4 + 0] = v.x;
            Bs[r][c4 + 1] = v.y;
            Bs[r][c4 + 2] = v.z;
            Bs[r][c4 + 3] = v.w;
        } else {
            // B is N x K row-major; we need Bs[k][n] = B[n][k]
            const int r  = tid >> 2;          // 0..63 (n)
            const int c4 = (tid & 3) * 4;     // 0,4,8,12 (k)
            const float4 v = *(const float4*)(B + (long long)(n0 + r) * ldb + k0 + c4);
            Bs[c4 + 0][r] = v.x;
            Bs[c4 + 1][r] = v.y;
            Bs[c4 + 2][r] = v.z;
            Bs[c4 + 3][r] = v.w;
        }
        __syncthreads();

        #pragma unroll
        for (int kk = 0; kk < BK; kk++) {
            float a[4], b[4];
            #pragma unroll
            for (int i = 0; i < 4; i++) a[i] = As[kk][ty + i * 16];
            #pragma unroll
            for (int j = 0; j < 4; j++) b[j] = Bs[kk][tx + j * 16];
            #pragma unroll
            for (int i = 0; i < 4; i++)
                #pragma unroll
                for (int j = 0; j < 4; j++)
                    acc[i][j] += a[i] * b[j];
        }
        __syncthreads();
    }

    #pragma unroll
    for (int i = 0; i < 4; i++) {
        const int m = m0 + ty + i * 16;
        #pragma unroll
        for (int j = 0; j < 4; j++) {
            const int n = n0 + tx + j * 16;
            float v = acc[i][j] * alpha;
            if (HAS_BIAS) v += bias[n];
            C[(long long)m * ldc + n] = v;
        }
    }
}

// ---------------------------------------------------------------------------
// Row softmax over 2048 columns, one block (256 threads) per row.
// Each thread owns 8 columns, held in registers (one exp per element).
// ---------------------------------------------------------------------------
__global__ void softmax_rows_kernel(float* __restrict__ attn)
{
    const long long row = blockIdx.x;
    float* p = attn + row * (long long)SEQ;
    const int t = threadIdx.x;   // 0..255
    __shared__ float red[256];

    float v[8];
    float m = -1e30f;
    #pragma unroll
    for (int i = 0; i < 8; i++) {
        v[i] = p[t + i * 256];
        m = fmaxf(m, v[i]);
    }
    red[t] = m;
    __syncthreads();
    for (int s = 128; s > 0; s >>= 1) {
        if (t < s) red[t] = fmaxf(red[t], red[t + s]);
        __syncthreads();
    }
    m = red[0];
    __syncthreads();

    float sum = 0.f;
    #pragma unroll
    for (int i = 0; i < 8; i++) {
        v[i] = __expf(v[i] - m);
        sum += v[i];
    }
    red[t] = sum;
    __syncthreads();
    for (int s = 128; s > 0; s >>= 1) {
        if (t < s) red[t] += red[t + s];
        __syncthreads();
    }
    const float inv = 1.f / red[0];

    #pragma unroll
    for (int i = 0; i < 8; i++)
        p[t + i * 256] = v[i] * inv;
}

// ---------------------------------------------------------------------------
extern "C" void kernel_launch(void* const* d_in, const int* in_sizes, int n_in,
                              void* d_out, int out_size)
{
    const float* q   = (const float*)d_in[0];
    const float* k   = (const float*)d_in[1];
    const float* v   = (const float*)d_in[2];
    const float* w_q = (const float*)d_in[3];
    const float* b_q = (const float*)d_in[4];
    const float* w_k = (const float*)d_in[5];
    const float* b_k = (const float*)d_in[6];
    const float* w_v = (const float*)d_in[7];
    const float* b_v = (const float*)d_in[8];
    const float* w_o = (const float*)d_in[9];
    const float* b_o = (const float*)d_in[10];

    float *gq, *gk, *gv, *gctx, *gattn;
    cudaGetSymbolAddress((void**)&gq,   g_q);
    cudaGetSymbolAddress((void**)&gk,   g_k);
    cudaGetSymbolAddress((void**)&gv,   g_v);
    cudaGetSymbolAddress((void**)&gctx, g_ctx);
    cudaGetSymbolAddress((void**)&gattn, g_attn);

    float* outp = (float*)d_out;
    const long long OUT_ELEMS  = (long long)MROWS * D_MODEL;                 // 3,145,728
    const long long ATTN_ELEMS = (long long)BATCH * NHEAD * SEQ * SEQ;       // 100,663,296
    float* attn = ((long long)out_size >= OUT_ELEMS + ATTN_ELEMS) ? (outp + OUT_ELEMS)
                                                                  : gattn;

    const dim3 tpb(16, 16);

    // --- Q/K/V projections: (4096 x 768) @ (768 x 768) + bias ---
    {
        const dim3 grid(D_MODEL / BN, MROWS / BM, 1);
        gemm_kernel<false, true><<<grid, tpb>>>(q, w_q, b_q, gq,
            D_MODEL, D_MODEL, D_MODEL, D_MODEL,
            1, 0, 0, 0, 0, 0, 0, 1.0f);
        gemm_kernel<false, true><<<grid, tpb>>>(k, w_k, b_k, gk,
            D_MODEL, D_MODEL, D_MODEL, D_MODEL,
            1, 0, 0, 0, 0, 0, 0, 1.0f);
        gemm_kernel<false, true><<<grid, tpb>>>(v, w_v, b_v, gv,
            D_MODEL, D_MODEL, D_MODEL, D_MODEL,
            1, 0, 0, 0, 0, 0, 0, 1.0f);
    }

    // --- Scores: per (b,h)  S = (1/8) * Qh @ Kh^T   (2048x64)@(64x2048) ---
    {
        const dim3 grid(SEQ / BN, SEQ / BM, BATCH * NHEAD);
        const float scale = 1.0f / 8.0f;   // 1/sqrt(64)
        gemm_kernel<true, false><<<grid, tpb>>>(gq, gk, nullptr, attn,
            DK, D_MODEL, D_MODEL, SEQ,
            NHEAD,
            (long long)SEQ * D_MODEL, DK,          // A offsets: b, h
            (long long)SEQ * D_MODEL, DK,          // B offsets: b, h
            (long long)NHEAD * SEQ * SEQ, (long long)SEQ * SEQ,  // C offsets
            scale);
    }

    // --- Softmax over each of the 49152 rows of 2048 ---
    softmax_rows_kernel<<<BATCH * NHEAD * SEQ, 256>>>(attn);

    // --- PV: per (b,h)  ctx_h = P @ Vh   (2048x2048)@(2048x64) ---
    {
        const dim3 grid(DK / BN, SEQ / BM, BATCH * NHEAD);
        gemm_kernel<false, false><<<grid, tpb>>>(attn, gv, nullptr, gctx,
            SEQ, SEQ, D_MODEL, D_MODEL,
            NHEAD,
            (long long)NHEAD * SEQ * SEQ, (long long)SEQ * SEQ,   // A offsets
            (long long)SEQ * D_MODEL, DK,                         // B offsets
            (long long)SEQ * D_MODEL, DK,                         // C offsets
            1.0f);
    }

    // --- Output projection: (4096 x 768) @ (768 x 768) + bias -> out ---
    {
        const dim3 grid(D_MODEL / BN, MROWS / BM, 1);
        gemm_kernel<false, true><<<grid, tpb>>>(gctx, w_o, b_o, outp,
            D_MODEL, D_MODEL, D_MODEL, D_MODEL,
            1, 0, 0, 0, 0, 0, 0, 1.0f);
    }
}

// round 2
// speedup vs baseline: 2.4485x; 2.4485x over previous
#include <cuda_runtime.h>
#include <math.h>
#include <stdint.h>

// Problem constants
#define D_MODEL 768
#define NHEAD   12
#define DK      64
#define BATCH   2
#define SEQ     2048
#define MROWS   (BATCH*SEQ)   // 4096

// Scratch in device globals (allocation-free rule)
__device__ float g_q[MROWS * D_MODEL];
__device__ float g_k[MROWS * D_MODEL];
__device__ float g_v[MROWS * D_MODEL];
__device__ float g_ctx[MROWS * D_MODEL];
// Fallback attention buffer if d_out only holds `out`
__device__ float g_attn[(size_t)BATCH * NHEAD * SEQ * SEQ];

// ---------------------------------------------------------------------------
// TF32 tensor-core GEMM: C = alpha * A * op(B) (+ bias)
// Block tile 128x64, BK=16. 256 threads = 8 warps in 4(M) x 2(N) layout,
// each warp computes a 32x32 tile via m16n8k8 TF32 MMA (2 m-frags x 4 n-frags).
// Batched over blockIdx.z with (z / zh, z % zh) stride offsets.
// All shapes are multiples of tile sizes (no bounds checks needed here).
// ---------------------------------------------------------------------------
#define BM 128
#define BN 64
#define BK 16

__device__ __forceinline__ uint32_t f2tf32(float x) {
    uint32_t r;
    asm("cvt.rna.tf32.f32 %0, %1;" : "=r"(r) : "f"(x));
    return r;
}

__device__ __forceinline__ void mma_tf32(float& d0, float& d1, float& d2, float& d3,
                                         uint32_t a0, uint32_t a1, uint32_t a2, uint32_t a3,
                                         uint32_t b0, uint32_t b1) {
    asm volatile(
        "mma.sync.aligned.m16n8k8.row.col.f32.tf32.tf32.f32 "
        "{%0,%1,%2,%3}, {%4,%5,%6,%7}, {%8,%9}, {%0,%1,%2,%3};\n"
        : "+f"(d0), "+f"(d1), "+f"(d2), "+f"(d3)
        : "r"(a0), "r"(a1), "r"(a2), "r"(a3), "r"(b0), "r"(b1));
}

#define APAD 8
#define BPAD 8

template <bool TRANS_B, bool HAS_BIAS>
__global__ void gemm_tf32_kernel(const float* __restrict__ A,
                                 const float* __restrict__ B,
                                 const float* __restrict__ bias,
                                 float* __restrict__ C,
                                 int K, int lda, int ldb, int ldc,
                                 int zh,
                                 long long sAb, long long sAh,
                                 long long sBb, long long sBh,
                                 long long sCb, long long sCh,
                                 float alpha)
{
    const int z  = blockIdx.z;
    const int zb = z / zh;
    const int zr = z % zh;
    A += zb * sAb + zr * sAh;
    B += zb * sBb + zr * sBh;
    C += zb * sCb + zr * sCh;

    // k-major smem tiles, padded so fragment loads are bank-conflict-free
    __shared__ uint32_t As[BK][BM + APAD];
    __shared__ uint32_t Bs[BK][BN + BPAD];

    const int tid   = threadIdx.x;          // 0..255
    const int warp  = tid >> 5;             // 0..7
    const int lane  = tid & 31;
    const int wm    = (warp & 3) * 32;      // warp M offset in block tile
    const int wn    = (warp >> 2) * 32;     // warp N offset in block tile
    const int gid   = lane >> 2;            // groupID 0..7
    const int tig   = lane & 3;             // thread in group 0..3

    const int m0 = blockIdx.y * BM;
    const int n0 = blockIdx.x * BN;

    // accum: 2 m-frags x 4 n-frags x 4 floats
    float acc[2][4][4] = {};

    for (int k0 = 0; k0 < K; k0 += BK) {
        // ---- Load A tile: BM x BK, float4 along k, store k-major (transposed)
        #pragma unroll
        for (int r0 = 0; r0 < BM; r0 += 64) {
            const int r  = r0 + (tid >> 2);        // row 0..127
            const int c4 = (tid & 3) * 4;          // k 0,4,8,12
            const float4 v = *(const float4*)(A + (long long)(m0 + r) * lda + k0 + c4);
            As[c4 + 0][r] = f2tf32(v.x);
            As[c4 + 1][r] = f2tf32(v.y);
            As[c4 + 2][r] = f2tf32(v.z);
            As[c4 + 3][r] = f2tf32(v.w);
        }
        // ---- Load B tile into Bs[k][n]
        if (!TRANS_B) {
            // B is K x N row-major: 16 rows x 64 cols = 256 float4
            const int r  = tid >> 4;               // k 0..15
            const int c4 = (tid & 15) * 4;         // n 0..60
            const float4 v = *(const float4*)(B + (long long)(k0 + r) * ldb + n0 + c4);
            Bs[r][c4 + 0] = f2tf32(v.x);
            Bs[r][c4 + 1] = f2tf32(v.y);
            Bs[r][c4 + 2] = f2tf32(v.z);
            Bs[r][c4 + 3] = f2tf32(v.w);
        } else {
            // B is N x K row-major; Bs[k][n] = B[n][k]
            const int r  = tid >> 2;               // n 0..63
            const int c4 = (tid & 3) * 4;          // k 0,4,8,12
            const float4 v = *(const float4*)(B + (long long)(n0 + r) * ldb + k0 + c4);
            Bs[c4 + 0][r] = f2tf32(v.x);
            Bs[c4 + 1][r] = f2tf32(v.y);
            Bs[c4 + 2][r] = f2tf32(v.z);
            Bs[c4 + 3][r] = f2tf32(v.w);
        }
        __syncthreads();

        #pragma unroll
        for (int kk = 0; kk < BK; kk += 8) {
            // A fragments: 2 x m16
            uint32_t af[2][4];
            #pragma unroll
            for (int i = 0; i < 2; i++) {
                const int row = wm + 16 * i + gid;
                af[i][0] = As[kk + tig    ][row];
                af[i][1] = As[kk + tig    ][row + 8];
                af[i][2] = As[kk + tig + 4][row];
                af[i][3] = As[kk + tig + 4][row + 8];
            }
            // B fragments: 4 x n8
            uint32_t bf[4][2];
            #pragma unroll
            for (int j = 0; j < 4; j++) {
                const int col = wn + 8 * j + gid;
                bf[j][0] = Bs[kk + tig    ][col];
                bf[j][1] = Bs[kk + tig + 4][col];
            }
            #pragma unroll
            for (int i = 0; i < 2; i++)
                #pragma unroll
                for (int j = 0; j < 4; j++)
                    mma_tf32(acc[i][j][0], acc[i][j][1], acc[i][j][2], acc[i][j][3],
                             af[i][0], af[i][1], af[i][2], af[i][3],
                             bf[j][0], bf[j][1]);
        }
        __syncthreads();
    }

    // ---- Epilogue
    #pragma unroll
    for (int i = 0; i < 2; i++) {
        const int row = m0 + wm + 16 * i + gid;
        #pragma unroll
        for (int j = 0; j < 4; j++) {
            const int col = n0 + wn + 8 * j + 2 * tig;
            float v0 = acc[i][j][0] * alpha;
            float v1 = acc[i][j][1] * alpha;
            float v2 = acc[i][j][2] * alpha;
            float v3 = acc[i][j][3] * alpha;
            if (HAS_BIAS) {
                v0 += bias[col];
                v1 += bias[col + 1];
                v2 += bias[col];
                v3 += bias[col + 1];
            }
            C[(long long)row * ldc + col]           = v0;
            C[(long long)row * ldc + col + 1]       = v1;
            C[(long long)(row + 8) * ldc + col]     = v2;
            C[(long long)(row + 8) * ldc + col + 1] = v3;
        }
    }
}

// ---------------------------------------------------------------------------
// Row softmax over 2048 columns, one block (256 threads) per row.
// ---------------------------------------------------------------------------
__global__ void softmax_rows_kernel(float* __restrict__ attn)
{
    const long long row = blockIdx.x;
    float* p = attn + row * (long long)SEQ;
    const int t = threadIdx.x;   // 0..255
    __shared__ float red[256];

    float v[8];
    float m = -1e30f;
    #pragma unroll
    for (int i = 0; i < 8; i++) {
        v[i] = p[t + i * 256];
        m = fmaxf(m, v[i]);
    }
    red[t] = m;
    __syncthreads();
    for (int s = 128; s > 0; s >>= 1) {
        if (t < s) red[t] = fmaxf(red[t], red[t + s]);
        __syncthreads();
    }
    m = red[0];
    __syncthreads();

    float sum = 0.f;
    #pragma unroll
    for (int i = 0; i < 8; i++) {
        v[i] = __expf(v[i] - m);
        sum += v[i];
    }
    red[t] = sum;
    __syncthreads();
    for (int s = 128; s > 0; s >>= 1) {
        if (t < s) red[t] += red[t + s];
        __syncthreads();
    }
    const float inv = 1.f / red[0];

    #pragma unroll
    for (int i = 0; i < 8; i++)
        p[t + i * 256] = v[i] * inv;
}

// ---------------------------------------------------------------------------
extern "C" void kernel_launch(void* const* d_in, const int* in_sizes, int n_in,
                              void* d_out, int out_size)
{
    const float* q   = (const float*)d_in[0];
    const float* k   = (const float*)d_in[1];
    const float* v   = (const float*)d_in[2];
    const float* w_q = (const float*)d_in[3];
    const float* b_q = (const float*)d_in[4];
    const float* w_k = (const float*)d_in[5];
    const float* b_k = (const float*)d_in[6];
    const float* w_v = (const float*)d_in[7];
    const float* b_v = (const float*)d_in[8];
    const float* w_o = (const float*)d_in[9];
    const float* b_o = (const float*)d_in[10];

    float *gq, *gk, *gv, *gctx, *gattn;
    cudaGetSymbolAddress((void**)&gq,   g_q);
    cudaGetSymbolAddress((void**)&gk,   g_k);
    cudaGetSymbolAddress((void**)&gv,   g_v);
    cudaGetSymbolAddress((void**)&gctx, g_ctx);
    cudaGetSymbolAddress((void**)&gattn, g_attn);

    float* outp = (float*)d_out;
    const long long OUT_ELEMS  = (long long)MROWS * D_MODEL;                 // 3,145,728
    const long long ATTN_ELEMS = (long long)BATCH * NHEAD * SEQ * SEQ;       // 100,663,296
    float* attn = ((long long)out_size >= OUT_ELEMS + ATTN_ELEMS) ? (outp + OUT_ELEMS)
                                                                  : gattn;

    const int TPB = 256;

    // --- Q/K/V projections: (4096 x 768) @ (768 x 768) + bias ---
    {
        const dim3 grid(D_MODEL / BN, MROWS / BM, 1);
        gemm_tf32_kernel<false, true><<<grid, TPB>>>(q, w_q, b_q, gq,
            D_MODEL, D_MODEL, D_MODEL, D_MODEL,
            1, 0, 0, 0, 0, 0, 0, 1.0f);
        gemm_tf32_kernel<false, true><<<grid, TPB>>>(k, w_k, b_k, gk,
            D_MODEL, D_MODEL, D_MODEL, D_MODEL,
            1, 0, 0, 0, 0, 0, 0, 1.0f);
        gemm_tf32_kernel<false, true><<<grid, TPB>>>(v, w_v, b_v, gv,
            D_MODEL, D_MODEL, D_MODEL, D_MODEL,
            1, 0, 0, 0, 0, 0, 0, 1.0f);
    }

    // --- Scores: per (b,h)  S = (1/8) * Qh @ Kh^T   (2048x64)@(64x2048)^T ---
    {
        const dim3 grid(SEQ / BN, SEQ / BM, BATCH * NHEAD);
        const float scale = 1.0f / 8.0f;   // 1/sqrt(64)
        gemm_tf32_kernel<true, false><<<grid, TPB>>>(gq, gk, nullptr, attn,
            DK, D_MODEL, D_MODEL, SEQ,
            NHEAD,
            (long long)SEQ * D_MODEL, DK,          // A offsets: b, h
            (long long)SEQ * D_MODEL, DK,          // B offsets: b, h
            (long long)NHEAD * SEQ * SEQ, (long long)SEQ * SEQ,  // C offsets
            scale);
    }

    // --- Softmax over each of the 49152 rows of 2048 ---
    softmax_rows_kernel<<<BATCH * NHEAD * SEQ, 256>>>(attn);

    // --- PV: per (b,h)  ctx_h = P @ Vh   (2048x2048)@(2048x64) ---
    {
        const dim3 grid(DK / BN, SEQ / BM, BATCH * NHEAD);
        gemm_tf32_kernel<false, false><<<grid, TPB>>>(attn, gv, nullptr, gctx,
            SEQ, SEQ, D_MODEL, D_MODEL,
            NHEAD,
            (long long)NHEAD * SEQ * SEQ, (long long)SEQ * SEQ,   // A offsets
            (long long)SEQ * D_MODEL, DK,                         // B offsets
            (long long)SEQ * D_MODEL, DK,                         // C offsets
            1.0f);
    }

    // --- Output projection: (4096 x 768) @ (768 x 768) + bias -> out ---
    {
        const dim3 grid(D_MODEL / BN, MROWS / BM, 1);
        gemm_tf32_kernel<false, true><<<grid, TPB>>>(gctx, w_o, b_o, outp,
            D_MODEL, D_MODEL, D_MODEL, D_MODEL,
            1, 0, 0, 0, 0, 0, 0, 1.0f);
    }
}

// round 3
// speedup vs baseline: 2.5226x; 1.0302x over previous
#include <cuda_runtime.h>
#include <math.h>
#include <stdint.h>

// Problem constants
#define D_MODEL 768
#define NHEAD   12
#define DK      64
#define BATCH   2
#define SEQ     2048
#define MROWS   (BATCH*SEQ)   // 4096

// Scratch in device globals (allocation-free rule)
__device__ float g_q[MROWS * D_MODEL];
__device__ float g_k[MROWS * D_MODEL];
__device__ float g_v[MROWS * D_MODEL];
__device__ float g_ctx[MROWS * D_MODEL];
// Fallback attention buffer if d_out only holds `out`
__device__ float g_attn[(size_t)BATCH * NHEAD * SEQ * SEQ];

// ---------------------------------------------------------------------------
// Common MMA helpers (TF32 m16n8k8)
// ---------------------------------------------------------------------------
__device__ __forceinline__ uint32_t f2tf32(float x) {
    uint32_t r;
    asm("cvt.rna.tf32.f32 %0, %1;" : "=r"(r) : "f"(x));
    return r;
}

__device__ __forceinline__ void mma_tf32(float& d0, float& d1, float& d2, float& d3,
                                         uint32_t a0, uint32_t a1, uint32_t a2, uint32_t a3,
                                         uint32_t b0, uint32_t b1) {
    asm volatile(
        "mma.sync.aligned.m16n8k8.row.col.f32.tf32.tf32.f32 "
        "{%0,%1,%2,%3}, {%4,%5,%6,%7}, {%8,%9}, {%0,%1,%2,%3};\n"
        : "+f"(d0), "+f"(d1), "+f"(d2), "+f"(d3)
        : "r"(a0), "r"(a1), "r"(a2), "r"(a3), "r"(b0), "r"(b1));
}

// ---------------------------------------------------------------------------
// Projection GEMM body: C = A(4096-row slab) @ B(768x768) + bias
// Block tile 128x64, BK=16. 256 threads = 8 warps (4M x 2N), 32x32 warp tile.
// Shapes hardcoded: K = lda = ldb = ldc = 768.
// ---------------------------------------------------------------------------
#define PBM 128
#define PBN 64
#define PBK 16

__device__ __forceinline__ void gemm_proj_body(const float* __restrict__ A,
                                               const float* __restrict__ B,
                                               const float* __restrict__ bias,
                                               float* __restrict__ C)
{
    __shared__ uint32_t As[PBK][PBM + 8];
    __shared__ uint32_t Bs[PBK][PBN + 8];

    const int tid  = threadIdx.x;
    const int warp = tid >> 5;
    const int lane = tid & 31;
    const int wm   = (warp & 3) * 32;
    const int wn   = (warp >> 2) * 32;
    const int gid  = lane >> 2;
    const int tig  = lane & 3;

    const int m0 = blockIdx.y * PBM;
    const int n0 = blockIdx.x * PBN;

    float acc[2][4][4] = {};

    for (int k0 = 0; k0 < D_MODEL; k0 += PBK) {
        // A tile: 128 x 16, float4 along k, stored k-major
        #pragma unroll
        for (int r0 = 0; r0 < PBM; r0 += 64) {
            const int r  = r0 + (tid >> 2);
            const int c4 = (tid & 3) * 4;
            const float4 v = *(const float4*)(A + (long long)(m0 + r) * D_MODEL + k0 + c4);
            As[c4 + 0][r] = f2tf32(v.x);
            As[c4 + 1][r] = f2tf32(v.y);
            As[c4 + 2][r] = f2tf32(v.z);
            As[c4 + 3][r] = f2tf32(v.w);
        }
        // B tile: 16 x 64
        {
            const int r  = tid >> 4;
            const int c4 = (tid & 15) * 4;
            const float4 v = *(const float4*)(B + (long long)(k0 + r) * D_MODEL + n0 + c4);
            Bs[r][c4 + 0] = f2tf32(v.x);
            Bs[r][c4 + 1] = f2tf32(v.y);
            Bs[r][c4 + 2] = f2tf32(v.z);
            Bs[r][c4 + 3] = f2tf32(v.w);
        }
        __syncthreads();

        #pragma unroll
        for (int kk = 0; kk < PBK; kk += 8) {
            uint32_t af[2][4];
            #pragma unroll
            for (int i = 0; i < 2; i++) {
                const int row = wm + 16 * i + gid;
                af[i][0] = As[kk + tig    ][row];
                af[i][1] = As[kk + tig    ][row + 8];
                af[i][2] = As[kk + tig + 4][row];
                af[i][3] = As[kk + tig + 4][row + 8];
            }
            uint32_t bf[4][2];
            #pragma unroll
            for (int j = 0; j < 4; j++) {
                const int col = wn + 8 * j + gid;
                bf[j][0] = Bs[kk + tig    ][col];
                bf[j][1] = Bs[kk + tig + 4][col];
            }
            #pragma unroll
            for (int i = 0; i < 2; i++)
                #pragma unroll
                for (int j = 0; j < 4; j++)
                    mma_tf32(acc[i][j][0], acc[i][j][1], acc[i][j][2], acc[i][j][3],
                             af[i][0], af[i][1], af[i][2], af[i][3],
                             bf[j][0], bf[j][1]);
        }
        __syncthreads();
    }

    #pragma unroll
    for (int i = 0; i < 2; i++) {
        const int row = m0 + wm + 16 * i + gid;
        #pragma unroll
        for (int j = 0; j < 4; j++) {
            const int col = n0 + wn + 8 * j + 2 * tig;
            const float b0 = bias[col];
            const float b1 = bias[col + 1];
            C[(long long)row * D_MODEL + col]           = acc[i][j][0] + b0;
            C[(long long)row * D_MODEL + col + 1]       = acc[i][j][1] + b1;
            C[(long long)(row + 8) * D_MODEL + col]     = acc[i][j][2] + b0;
            C[(long long)(row + 8) * D_MODEL + col + 1] = acc[i][j][3] + b1;
        }
    }
}

// QKV combined: blockIdx.z selects which projection this block computes.
__global__ __launch_bounds__(256) void qkv_proj_kernel(
    const float* __restrict__ q, const float* __restrict__ k, const float* __restrict__ v,
    const float* __restrict__ wq, const float* __restrict__ wk, const float* __restrict__ wv,
    const float* __restrict__ bq, const float* __restrict__ bk, const float* __restrict__ bv,
    float* __restrict__ oq, float* __restrict__ ok, float* __restrict__ ov)
{
    const int z = blockIdx.z;
    const float* A    = (z == 0) ? q  : (z == 1) ? k  : v;
    const float* B    = (z == 0) ? wq : (z == 1) ? wk : wv;
    const float* bias = (z == 0) ? bq : (z == 1) ? bk : bv;
    float*       C    = (z == 0) ? oq : (z == 1) ? ok : ov;
    gemm_proj_body(A, B, bias, C);
}

__global__ __launch_bounds__(256) void out_proj_kernel(
    const float* __restrict__ A, const float* __restrict__ B,
    const float* __restrict__ bias, float* __restrict__ C)
{
    gemm_proj_body(A, B, bias, C);
}

// ---------------------------------------------------------------------------
// Fused attention: per (b,h) and 128-row q tile:
//   pass 1: S = Q K^T / 8 (TF32 MMA), rowsum += exp(S)
//   pass 2: recompute S, p = exp(S) * inv_rowsum, write p (coalesced via smem),
//           ctx += p @ V (TF32 MMA)
// 256 threads = 8 warps (4M x 2N), key tiles of 64, dk = 64.
// ---------------------------------------------------------------------------
struct SmemFused {
    uint32_t Qs[64][136];   // [dk][q]   (k-major, tf32)
    uint32_t Ks[64][72];    // [dk][key] (k-major, tf32)
    uint32_t Vs[64][72];    // [key][dk] (tf32)
    float    Ps[128][68];   // [q][key]  (fp32 probabilities)
    float    rowsum[128];
};

__global__ __launch_bounds__(256, 2) void fused_attn_kernel(
    const float* __restrict__ Qg, const float* __restrict__ Kg, const float* __restrict__ Vg,
    float* __restrict__ attn, float* __restrict__ ctx)
{
    extern __shared__ char smraw[];
    SmemFused& sm = *reinterpret_cast<SmemFused*>(smraw);

    const int tid  = threadIdx.x;
    const int warp = tid >> 5;
    const int lane = tid & 31;
    const int gid  = lane >> 2;
    const int tig  = lane & 3;
    const int wm   = (warp & 3) * 32;
    const int wn   = (warp >> 2) * 32;

    const int q0 = blockIdx.x * 128;
    const int z  = blockIdx.y;
    const int b  = z / NHEAD;
    const int h  = z % NHEAD;

    const float* qb = Qg + (long long)b * SEQ * D_MODEL + h * DK;
    const float* kb = Kg + (long long)b * SEQ * D_MODEL + h * DK;
    const float* vb = Vg + (long long)b * SEQ * D_MODEL + h * DK;
    float* ab = attn + (long long)z * SEQ * SEQ;
    float* cb = ctx + (long long)b * SEQ * D_MODEL + h * DK;

    // ---- Load Q tile (128 x 64) into Qs[dk][q], once
    #pragma unroll
    for (int it = 0; it < 8; it++) {
        const int idx = tid + it * 256;          // 0..2047
        const int row = idx >> 4;                // q row 0..127
        const int c4  = (idx & 15) * 4;          // dk 0..60
        const float4 v = *(const float4*)(qb + (long long)(q0 + row) * D_MODEL + c4);
        sm.Qs[c4 + 0][row] = f2tf32(v.x);
        sm.Qs[c4 + 1][row] = f2tf32(v.y);
        sm.Qs[c4 + 2][row] = f2tf32(v.z);
        sm.Qs[c4 + 3][row] = f2tf32(v.w);
    }
    if (tid < 128) sm.rowsum[tid] = 0.f;
    __syncthreads();

    // =========================== PASS 1: row sums ===========================
    for (int t = 0; t < SEQ / 64; t++) {
        const int n0 = t * 64;
        // Load K tile (64 keys x 64 dk) into Ks[dk][key]
        #pragma unroll
        for (int it = 0; it < 4; it++) {
            const int idx = tid + it * 256;      // 0..1023
            const int key = idx >> 4;
            const int c4  = (idx & 15) * 4;
            const float4 v = *(const float4*)(kb + (long long)(n0 + key) * D_MODEL + c4);
            sm.Ks[c4 + 0][key] = f2tf32(v.x);
            sm.Ks[c4 + 1][key] = f2tf32(v.y);
            sm.Ks[c4 + 2][key] = f2tf32(v.z);
            sm.Ks[c4 + 3][key] = f2tf32(v.w);
        }
        __syncthreads();

        float acc[2][4][4] = {};
        #pragma unroll
        for (int kk = 0; kk < 64; kk += 8) {
            uint32_t af[2][4];
            #pragma unroll
            for (int i = 0; i < 2; i++) {
                const int row = wm + 16 * i + gid;
                af[i][0] = sm.Qs[kk + tig    ][row];
                af[i][1] = sm.Qs[kk + tig    ][row + 8];
                af[i][2] = sm.Qs[kk + tig + 4][row];
                af[i][3] = sm.Qs[kk + tig + 4][row + 8];
            }
            uint32_t bf[4][2];
            #pragma unroll
            for (int j = 0; j < 4; j++) {
                const int col = wn + 8 * j + gid;
                bf[j][0] = sm.Ks[kk + tig    ][col];
                bf[j][1] = sm.Ks[kk + tig + 4][col];
            }
            #pragma unroll
            for (int i = 0; i < 2; i++)
                #pragma unroll
                for (int j = 0; j < 4; j++)
                    mma_tf32(acc[i][j][0], acc[i][j][1], acc[i][j][2], acc[i][j][3],
                             af[i][0], af[i][1], af[i][2], af[i][3],
                             bf[j][0], bf[j][1]);
        }

        // exp + row-sum reduction
        #pragma unroll
        for (int i = 0; i < 2; i++) {
            float s0 = 0.f, s1 = 0.f;
            #pragma unroll
            for (int j = 0; j < 4; j++) {
                s0 += __expf(acc[i][j][0] * 0.125f) + __expf(acc[i][j][1] * 0.125f);
                s1 += __expf(acc[i][j][2] * 0.125f) + __expf(acc[i][j][3] * 0.125f);
            }
            s0 += __shfl_xor_sync(0xffffffffu, s0, 1);
            s0 += __shfl_xor_sync(0xffffffffu, s0, 2);
            s1 += __shfl_xor_sync(0xffffffffu, s1, 1);
            s1 += __shfl_xor_sync(0xffffffffu, s1, 2);
            if (tig == 0) {
                atomicAdd(&sm.rowsum[wm + 16 * i + gid],     s0);
                atomicAdd(&sm.rowsum[wm + 16 * i + gid + 8], s1);
            }
        }
        __syncthreads();
    }

    if (tid < 128) sm.rowsum[tid] = 1.0f / sm.rowsum[tid];
    __syncthreads();

    // ====================== PASS 2: write p, accumulate PV ==================
    float cacc[2][4][4] = {};
    for (int t = 0; t < SEQ / 64; t++) {
        const int n0 = t * 64;
        // K tile
        #pragma unroll
        for (int it = 0; it < 4; it++) {
            const int idx = tid + it * 256;
            const int key = idx >> 4;
            const int c4  = (idx & 15) * 4;
            const float4 v = *(const float4*)(kb + (long long)(n0 + key) * D_MODEL + c4);
            sm.Ks[c4 + 0][key] = f2tf32(v.x);
            sm.Ks[c4 + 1][key] = f2tf32(v.y);
            sm.Ks[c4 + 2][key] = f2tf32(v.z);
            sm.Ks[c4 + 3][key] = f2tf32(v.w);
        }
        // V tile (row-major keys x dk)
        #pragma unroll
        for (int it = 0; it < 4; it++) {
            const int idx = tid + it * 256;
            const int key = idx >> 4;
            const int c4  = (idx & 15) * 4;
            const float4 v = *(const float4*)(vb + (long long)(n0 + key) * D_MODEL + c4);
            uint4 u;
            u.x = f2tf32(v.x); u.y = f2tf32(v.y); u.z = f2tf32(v.z); u.w = f2tf32(v.w);
            *(uint4*)&sm.Vs[key][c4] = u;
        }
        __syncthreads();

        // Scores MMA (same as pass 1)
        float acc[2][4][4] = {};
        #pragma unroll
        for (int kk = 0; kk < 64; kk += 8) {
            uint32_t af[2][4];
            #pragma unroll
            for (int i = 0; i < 2; i++) {
                const int row = wm + 16 * i + gid;
                af[i][0] = sm.Qs[kk + tig    ][row];
                af[i][1] = sm.Qs[kk + tig    ][row + 8];
                af[i][2] = sm.Qs[kk + tig + 4][row];
                af[i][3] = sm.Qs[kk + tig + 4][row + 8];
            }
            uint32_t bf[4][2];
            #pragma unroll
            for (int j = 0; j < 4; j++) {
                const int col = wn + 8 * j + gid;
                bf[j][0] = sm.Ks[kk + tig    ][col];
                bf[j][1] = sm.Ks[kk + tig + 4][col];
            }
            #pragma unroll
            for (int i = 0; i < 2; i++)
                #pragma unroll
                for (int j = 0; j < 4; j++)
                    mma_tf32(acc[i][j][0], acc[i][j][1], acc[i][j][2], acc[i][j][3],
                             af[i][0], af[i][1], af[i][2], af[i][3],
                             bf[j][0], bf[j][1]);
        }

        // p = exp(s)*inv, stage into Ps
        #pragma unroll
        for (int i = 0; i < 2; i++) {
            const int rA = wm + 16 * i + gid;
            const float inv0 = sm.rowsum[rA];
            const float inv1 = sm.rowsum[rA + 8];
            #pragma unroll
            for (int j = 0; j < 4; j++) {
                const int col = wn + 8 * j + 2 * tig;
                float2 p01, p23;
                p01.x = __expf(acc[i][j][0] * 0.125f) * inv0;
                p01.y = __expf(acc[i][j][1] * 0.125f) * inv0;
                p23.x = __expf(acc[i][j][2] * 0.125f) * inv1;
                p23.y = __expf(acc[i][j][3] * 0.125f) * inv1;
                *(float2*)&sm.Ps[rA][col]     = p01;
                *(float2*)&sm.Ps[rA + 8][col] = p23;
            }
        }
        __syncthreads();

        // Write attn tile to gmem, coalesced float4
        #pragma unroll
        for (int it = 0; it < 8; it++) {
            const int idx = tid + it * 256;      // 0..2047
            const int row = idx >> 4;
            const int c4  = (idx & 15) * 4;
            const float4 v = *(const float4*)&sm.Ps[row][c4];
            *(float4*)(ab + (long long)(q0 + row) * SEQ + n0 + c4) = v;
        }

        // PV MMA: ctx += p @ V  (A = Ps, B = Vs, k = key dim)
        #pragma unroll
        for (int kk = 0; kk < 64; kk += 8) {
            uint32_t af[2][4];
            #pragma unroll
            for (int i = 0; i < 2; i++) {
                const int row = wm + 16 * i + gid;
                af[i][0] = f2tf32(sm.Ps[row    ][kk + tig    ]);
                af[i][1] = f2tf32(sm.Ps[row + 8][kk + tig    ]);
                af[i][2] = f2tf32(sm.Ps[row    ][kk + tig + 4]);
                af[i][3] = f2tf32(sm.Ps[row + 8][kk + tig + 4]);
            }
            uint32_t bf[4][2];
            #pragma unroll
            for (int j = 0; j < 4; j++) {
                const int col = wn + 8 * j + gid;
                bf[j][0] = sm.Vs[kk + tig    ][col];
                bf[j][1] = sm.Vs[kk + tig + 4][col];
            }
            #pragma unroll
            for (int i = 0; i < 2; i++)
                #pragma unroll
                for (int j = 0; j < 4; j++)
                    mma_tf32(cacc[i][j][0], cacc[i][j][1], cacc[i][j][2], cacc[i][j][3],
                             af[i][0], af[i][1], af[i][2], af[i][3],
                             bf[j][0], bf[j][1]);
        }
        __syncthreads();
    }

    // ---- ctx epilogue: rows q0+.., cols h*64+..
    #pragma unroll
    for (int i = 0; i < 2; i++) {
        const int row = q0 + wm + 16 * i + gid;
        #pragma unroll
        for (int j = 0; j < 4; j++) {
            const int col = wn + 8 * j + 2 * tig;
            float2 v01, v23;
            v01.x = cacc[i][j][0]; v01.y = cacc[i][j][1];
            v23.x = cacc[i][j][2]; v23.y = cacc[i][j][3];
            *(float2*)(cb + (long long)row * D_MODEL + col)       = v01;
            *(float2*)(cb + (long long)(row + 8) * D_MODEL + col) = v23;
        }
    }
}

// ---------------------------------------------------------------------------
extern "C" void kernel_launch(void* const* d_in, const int* in_sizes, int n_in,
                              void* d_out, int out_size)
{
    const float* q   = (const float*)d_in[0];
    const float* k   = (const float*)d_in[1];
    const float* v   = (const float*)d_in[2];
    const float* w_q = (const float*)d_in[3];
    const float* b_q = (const float*)d_in[4];
    const float* w_k = (const float*)d_in[5];
    const float* b_k = (const float*)d_in[6];
    const float* w_v = (const float*)d_in[7];
    const float* b_v = (const float*)d_in[8];
    const float* w_o = (const float*)d_in[9];
    const float* b_o = (const float*)d_in[10];

    float *gq, *gk, *gv, *gctx, *gattn;
    cudaGetSymbolAddress((void**)&gq,   g_q);
    cudaGetSymbolAddress((void**)&gk,   g_k);
    cudaGetSymbolAddress((void**)&gv,   g_v);
    cudaGetSymbolAddress((void**)&gctx, g_ctx);
    cudaGetSymbolAddress((void**)&gattn, g_attn);

    float* outp = (float*)d_out;
    const long long OUT_ELEMS  = (long long)MROWS * D_MODEL;
    const long long ATTN_ELEMS = (long long)BATCH * NHEAD * SEQ * SEQ;
    float* attn = ((long long)out_size >= OUT_ELEMS + ATTN_ELEMS) ? (outp + OUT_ELEMS)
                                                                  : gattn;

    // --- QKV projections (one launch, z selects q/k/v) ---
    {
        const dim3 grid(D_MODEL / PBN, MROWS / PBM, 3);
        qkv_proj_kernel<<<grid, 256>>>(q, k, v, w_q, w_k, w_v, b_q, b_k, b_v,
                                       gq, gk, gv);
    }

    // --- Fused attention: scores + softmax + attn write + PV ---
    {
        static int smem_set = 0;
        const int smem_bytes = (int)sizeof(SmemFused);
        if (!smem_set) {
            cudaFuncSetAttribute(fused_attn_kernel,
                                 cudaFuncAttributeMaxDynamicSharedMemorySize, smem_bytes);
            smem_set = 1;
        }
        const dim3 grid(SEQ / 128, BATCH * NHEAD);
        fused_attn_kernel<<<grid, 256, smem_bytes>>>(gq, gk, gv, attn, gctx);
    }

    // --- Output projection ---
    {
        const dim3 grid(D_MODEL / PBN, MROWS / PBM, 1);
        out_proj_kernel<<<grid, 256>>>(gctx, w_o, b_o, outp);
    }
}

// round 5
// speedup vs baseline: 3.6165x; 1.4336x over previous
#include <cuda_runtime.h>
#include <cuda_fp16.h>
#include <math.h>
#include <stdint.h>

// Problem constants
#define D_MODEL 768
#define NHEAD   12
#define DK      64
#define BATCH   2
#define SEQ     2048
#define MROWS   (BATCH*SEQ)   // 4096

// Scratch in device globals (allocation-free rule)
__device__ float g_q[MROWS * D_MODEL];
__device__ float g_k[MROWS * D_MODEL];
__device__ float g_v[MROWS * D_MODEL];
__device__ float g_ctx[MROWS * D_MODEL];
__device__ float g_inv[BATCH * NHEAD * SEQ];
// Fallback attention buffer if d_out only holds `out`
__device__ float g_attn[(size_t)BATCH * NHEAD * SEQ * SEQ];

// ---------------------------------------------------------------------------
// Helpers
// ---------------------------------------------------------------------------
__device__ __forceinline__ uint32_t packh2(float x, float y) {
    __half2 h = __floats2half2_rn(x, y);
    return *reinterpret_cast<uint32_t*>(&h);
}

__device__ __forceinline__ void mma_f16(float* d, const uint32_t* a, const uint32_t* b) {
    asm volatile(
        "mma.sync.aligned.m16n8k16.row.col.f32.f16.f16.f32 "
        "{%0,%1,%2,%3}, {%4,%5,%6,%7}, {%8,%9}, {%0,%1,%2,%3};\n"
        : "+f"(d[0]), "+f"(d[1]), "+f"(d[2]), "+f"(d[3])
        : "r"(a[0]), "r"(a[1]), "r"(a[2]), "r"(a[3]), "r"(b[0]), "r"(b[1]));
}

// ---------------------------------------------------------------------------
// Projection GEMM: C = A(4096x768) @ B(768x768) + bias, fp16 MMA, fp32 accum.
// Block tile 128x64, BK=32. 256 threads = 8 warps (4M x 2N), 32x32 warp tile.
// As[m][k] natural (k-contig halves); Bs[n][k] transposed (k-contig halves).
// ---------------------------------------------------------------------------
#define PBK 32
#define ALD 40   // k-ld of As in halves (32 + 8 pad -> 20-word stride, conflict-free frags)
#define BLD 40

__device__ __forceinline__ void gemm_proj_body(const float* __restrict__ A,
                                               const float* __restrict__ B,
                                               const float* __restrict__ bias,
                                               float* __restrict__ C)
{
    __shared__ __half As[128][ALD];
    __shared__ __half Bs[64][BLD];

    const int tid  = threadIdx.x;
    const int warp = tid >> 5;
    const int lane = tid & 31;
    const int gid  = lane >> 2;
    const int tig  = lane & 3;
    const int wm   = (warp & 3) * 32;
    const int wn   = (warp >> 2) * 32;

    const int m0 = blockIdx.y * 128;
    const int n0 = blockIdx.x * 64;

    float acc[2][4][4] = {};

    for (int k0 = 0; k0 < D_MODEL; k0 += PBK) {
        // ---- A tile: 128 x 32 halves, natural layout
        #pragma unroll
        for (int it = 0; it < 4; it++) {
            const int idx = tid + it * 256;          // 0..1023
            const int row = idx >> 3;                // 0..127
            const int c4  = (idx & 7) * 4;           // 0..28
            const float4 v = *(const float4*)(A + (long long)(m0 + row) * D_MODEL + k0 + c4);
            *(uint32_t*)&As[row][c4]     = packh2(v.x, v.y);
            *(uint32_t*)&As[row][c4 + 2] = packh2(v.z, v.w);
        }
        // ---- B tile transposed: Bs[n][k], built from k-row pairs
        {
            const int kp = tid & 15;                 // k-pair 0..15
            const int c4 = (tid >> 4) * 4;           // n 0..60
            const float* bp = B + (long long)(k0 + 2 * kp) * D_MODEL + n0 + c4;
            const float4 lo = *(const float4*)bp;
            const float4 hi = *(const float4*)(bp + D_MODEL);
            *(uint32_t*)&Bs[c4 + 0][2 * kp] = packh2(lo.x, hi.x);
            *(uint32_t*)&Bs[c4 + 1][2 * kp] = packh2(lo.y, hi.y);
            *(uint32_t*)&Bs[c4 + 2][2 * kp] = packh2(lo.z, hi.z);
            *(uint32_t*)&Bs[c4 + 3][2 * kp] = packh2(lo.w, hi.w);
        }
        __syncthreads();

        #pragma unroll
        for (int kk = 0; kk < PBK; kk += 16) {
            uint32_t af[2][4];
            #pragma unroll
            for (int i = 0; i < 2; i++) {
                const int row = wm + 16 * i + gid;
                af[i][0] = *(const uint32_t*)&As[row    ][kk + 2 * tig];
                af[i][1] = *(const uint32_t*)&As[row + 8][kk + 2 * tig];
                af[i][2] = *(const uint32_t*)&As[row    ][kk + 2 * tig + 8];
                af[i][3] = *(const uint32_t*)&As[row + 8][kk + 2 * tig + 8];
            }
            uint32_t bf[4][2];
            #pragma unroll
            for (int j = 0; j < 4; j++) {
                const int col = wn + 8 * j + gid;
                bf[j][0] = *(const uint32_t*)&Bs[col][kk + 2 * tig];
                bf[j][1] = *(const uint32_t*)&Bs[col][kk + 2 * tig + 8];
            }
            #pragma unroll
            for (int i = 0; i < 2; i++)
                #pragma unroll
                for (int j = 0; j < 4; j++)
                    mma_f16(acc[i][j], af[i], bf[j]);
        }
        __syncthreads();
    }

    #pragma unroll
    for (int i = 0; i < 2; i++) {
        const int row = m0 + wm + 16 * i + gid;
        #pragma unroll
        for (int j = 0; j < 4; j++) {
            const int col = n0 + wn + 8 * j + 2 * tig;
            const float b0 = bias[col];
            const float b1 = bias[col + 1];
            float2 v01, v23;
            v01.x = acc[i][j][0] + b0; v01.y = acc[i][j][1] + b1;
            v23.x = acc[i][j][2] + b0; v23.y = acc[i][j][3] + b1;
            *(float2*)(C + (long long)row * D_MODEL + col)       = v01;
            *(float2*)(C + (long long)(row + 8) * D_MODEL + col) = v23;
        }
    }
}

__global__ __launch_bounds__(256, 3) void qkv_proj_kernel(
    const float* __restrict__ q, const float* __restrict__ k, const float* __restrict__ v,
    const float* __restrict__ wq, const float* __restrict__ wk, const float* __restrict__ wv,
    const float* __restrict__ bq, const float* __restrict__ bk, const float* __restrict__ bv,
    float* __restrict__ oq, float* __restrict__ ok, float* __restrict__ ov)
{
    const int z = blockIdx.z;
    const float* A    = (z == 0) ? q  : (z == 1) ? k  : v;
    const float* B    = (z == 0) ? wq : (z == 1) ? wk : wv;
    const float* bias = (z == 0) ? bq : (z == 1) ? bk : bv;
    float*       C    = (z == 0) ? oq : (z == 1) ? ok : ov;
    gemm_proj_body(A, B, bias, C);
}

__global__ __launch_bounds__(256, 3) void out_proj_kernel(
    const float* __restrict__ A, const float* __restrict__ B,
    const float* __restrict__ bias, float* __restrict__ C)
{
    gemm_proj_body(A, B, bias, C);
}

// ---------------------------------------------------------------------------
// Kernel A (scores): per (z, q-tile 128):
//   S = Q K^T / 8 (fp16 MMA), write exp(S) (UNNORMALIZED) to attn, rowsum -> g_inv
// ---------------------------------------------------------------------------
#define QLD 72   // 64 + 8 pad (36-word stride -> conflict-free fragment LDS)

__global__ __launch_bounds__(256, 3) void scores_kernel(
    const float* __restrict__ Qg, const float* __restrict__ Kg,
    float* __restrict__ attn)
{
    __shared__ __half Qs[128][QLD];
    __shared__ __half Ks[64][QLD];
    __shared__ float  rowsum[128];

    const int tid  = threadIdx.x;
    const int warp = tid >> 5;
    const int lane = tid & 31;
    const int gid  = lane >> 2;
    const int tig  = lane & 3;
    const int wm   = (warp & 3) * 32;
    const int wn   = (warp >> 2) * 32;

    const int q0 = blockIdx.x * 128;
    const int z  = blockIdx.y;
    const int b  = z / NHEAD;
    const int h  = z % NHEAD;

    const float* qb = Qg + (long long)b * SEQ * D_MODEL + h * DK;
    const float* kb = Kg + (long long)b * SEQ * D_MODEL + h * DK;
    float* ab = attn + (long long)z * SEQ * SEQ;

    // Load Q tile (128 x 64) as halves
    #pragma unroll
    for (int it = 0; it < 8; it++) {
        const int idx = tid + it * 256;
        const int row = idx >> 4;
        const int c4  = (idx & 15) * 4;
        const float4 v = *(const float4*)(qb + (long long)(q0 + row) * D_MODEL + c4);
        *(uint32_t*)&Qs[row][c4]     = packh2(v.x, v.y);
        *(uint32_t*)&Qs[row][c4 + 2] = packh2(v.z, v.w);
    }
    if (tid < 128) rowsum[tid] = 0.f;
    __syncthreads();

    for (int t = 0; t < SEQ / 64; t++) {
        const int n0 = t * 64;
        // K tile (64 x 64)
        #pragma unroll
        for (int it = 0; it < 4; it++) {
            const int idx = tid + it * 256;
            const int key = idx >> 4;
            const int c4  = (idx & 15) * 4;
            const float4 v = *(const float4*)(kb + (long long)(n0 + key) * D_MODEL + c4);
            *(uint32_t*)&Ks[key][c4]     = packh2(v.x, v.y);
            *(uint32_t*)&Ks[key][c4 + 2] = packh2(v.z, v.w);
        }
        __syncthreads();

        float acc[2][4][4] = {};
        #pragma unroll
        for (int kk = 0; kk < 64; kk += 16) {
            uint32_t af[2][4];
            #pragma unroll
            for (int i = 0; i < 2; i++) {
                const int row = wm + 16 * i + gid;
                af[i][0] = *(const uint32_t*)&Qs[row    ][kk + 2 * tig];
                af[i][1] = *(const uint32_t*)&Qs[row + 8][kk + 2 * tig];
                af[i][2] = *(const uint32_t*)&Qs[row    ][kk + 2 * tig + 8];
                af[i][3] = *(const uint32_t*)&Qs[row + 8][kk + 2 * tig + 8];
            }
            uint32_t bf[4][2];
            #pragma unroll
            for (int j = 0; j < 4; j++) {
                const int col = wn + 8 * j + gid;
                bf[j][0] = *(const uint32_t*)&Ks[col][kk + 2 * tig];
                bf[j][1] = *(const uint32_t*)&Ks[col][kk + 2 * tig + 8];
            }
            #pragma unroll
            for (int i = 0; i < 2; i++)
                #pragma unroll
                for (int j = 0; j < 4; j++)
                    mma_f16(acc[i][j], af[i], bf[j]);
        }
        __syncthreads();   // all warps done with Ks before next tile's store

        // exp epilogue: write unnormalized exp(s) to attn, accumulate rowsum
        #pragma unroll
        for (int i = 0; i < 2; i++) {
            const int r = wm + 16 * i + gid;
            float s0 = 0.f, s1 = 0.f;
            #pragma unroll
            for (int j = 0; j < 4; j++) {
                const int col = n0 + wn + 8 * j + 2 * tig;
                float2 e01, e23;
                e01.x = __expf(acc[i][j][0] * 0.125f);
                e01.y = __expf(acc[i][j][1] * 0.125f);
                e23.x = __expf(acc[i][j][2] * 0.125f);
                e23.y = __expf(acc[i][j][3] * 0.125f);
                *(float2*)(ab + (long long)(q0 + r) * SEQ + col)     = e01;
                *(float2*)(ab + (long long)(q0 + r + 8) * SEQ + col) = e23;
                s0 += e01.x + e01.y;
                s1 += e23.x + e23.y;
            }
            s0 += __shfl_xor_sync(0xffffffffu, s0, 1);
            s0 += __shfl_xor_sync(0xffffffffu, s0, 2);
            s1 += __shfl_xor_sync(0xffffffffu, s1, 1);
            s1 += __shfl_xor_sync(0xffffffffu, s1, 2);
            if (tig == 0) {
                atomicAdd(&rowsum[r], s0);
                atomicAdd(&rowsum[r + 8], s1);
            }
        }
    }

    __syncthreads();
    if (tid < 128) g_inv[(long long)z * SEQ + q0 + tid] = 1.0f / rowsum[tid];
}

// ---------------------------------------------------------------------------
// Kernel B (normalize + PV): per (z, q-tile 128):
//   read attn tiles, scale by inv (in place, exact), stash half(p), ctx = P @ V
// ---------------------------------------------------------------------------
__global__ __launch_bounds__(256, 3) void pv_kernel(
    const float* __restrict__ Vg, float* __restrict__ attn, float* __restrict__ ctx)
{
    __shared__ __half Ps[128][QLD];
    __shared__ __half Vs[64][QLD];    // [dk][key] transposed
    __shared__ float  invs[128];

    const int tid  = threadIdx.x;
    const int warp = tid >> 5;
    const int lane = tid & 31;
    const int gid  = lane >> 2;
    const int tig  = lane & 3;
    const int wm   = (warp & 3) * 32;
    const int wn   = (warp >> 2) * 32;

    const int q0 = blockIdx.x * 128;
    const int z  = blockIdx.y;
    const int b  = z / NHEAD;
    const int h  = z % NHEAD;

    const float* vb = Vg + (long long)b * SEQ * D_MODEL + h * DK;
    float* ab = attn + (long long)z * SEQ * SEQ;
    float* cb = ctx + (long long)b * SEQ * D_MODEL + h * DK;

    if (tid < 128) invs[tid] = g_inv[(long long)z * SEQ + q0 + tid];
    __syncthreads();

    float cacc[2][4][4] = {};

    for (int t = 0; t < SEQ / 64; t++) {
        const int n0 = t * 64;

        // p-tile: load exp, normalize in place, write back, stash as half
        #pragma unroll
        for (int it = 0; it < 8; it++) {
            const int idx = tid + it * 256;
            const int row = idx >> 4;
            const int c4  = (idx & 15) * 4;
            float* p = ab + (long long)(q0 + row) * SEQ + n0 + c4;
            float4 v = *(const float4*)p;
            const float inv = invs[row];
            v.x *= inv; v.y *= inv; v.z *= inv; v.w *= inv;
            *(float4*)p = v;
            *(uint32_t*)&Ps[row][c4]     = packh2(v.x, v.y);
            *(uint32_t*)&Ps[row][c4 + 2] = packh2(v.z, v.w);
        }
        // V tile transposed: Vs[dk][key]
        #pragma unroll
        for (int it = 0; it < 2; it++) {
            const int c4 = ((tid >> 5) + it * 8) * 4;   // dk group 0..60
            const int kp = tid & 31;                    // key pair
            const float* vp = vb + (long long)(n0 + 2 * kp) * D_MODEL + c4;
            const float4 lo = *(const float4*)vp;
            const float4 hi = *(const float4*)(vp + D_MODEL);
            *(uint32_t*)&Vs[c4 + 0][2 * kp] = packh2(lo.x, hi.x);
            *(uint32_t*)&Vs[c4 + 1][2 * kp] = packh2(lo.y, hi.y);
            *(uint32_t*)&Vs[c4 + 2][2 * kp] = packh2(lo.z, hi.z);
            *(uint32_t*)&Vs[c4 + 3][2 * kp] = packh2(lo.w, hi.w);
        }
        __syncthreads();

        #pragma unroll
        for (int kk = 0; kk < 64; kk += 16) {
            uint32_t af[2][4];
            #pragma unroll
            for (int i = 0; i < 2; i++) {
                const int row = wm + 16 * i + gid;
                af[i][0] = *(const uint32_t*)&Ps[row    ][kk + 2 * tig];
                af[i][1] = *(const uint32_t*)&Ps[row + 8][kk + 2 * tig];
                af[i][2] = *(const uint32_t*)&Ps[row    ][kk + 2 * tig + 8];
                af[i][3] = *(const uint32_t*)&Ps[row + 8][kk + 2 * tig + 8];
            }
            uint32_t bf[4][2];
            #pragma unroll
            for (int j = 0; j < 4; j++) {
                const int col = wn + 8 * j + gid;   // dk column
                bf[j][0] = *(const uint32_t*)&Vs[col][kk + 2 * tig];
                bf[j][1] = *(const uint32_t*)&Vs[col][kk + 2 * tig + 8];
            }
            #pragma unroll
            for (int i = 0; i < 2; i++)
                #pragma unroll
                for (int j = 0; j < 4; j++)
                    mma_f16(cacc[i][j], af[i], bf[j]);
        }
        __syncthreads();
    }

    // ctx epilogue (already normalized)
    #pragma unroll
    for (int i = 0; i < 2; i++) {
        const int row = q0 + wm + 16 * i + gid;
        #pragma unroll
        for (int j = 0; j < 4; j++) {
            const int col = wn + 8 * j + 2 * tig;
            float2 v01, v23;
            v01.x = cacc[i][j][0]; v01.y = cacc[i][j][1];
            v23.x = cacc[i][j][2]; v23.y = cacc[i][j][3];
            *(float2*)(cb + (long long)row * D_MODEL + col)       = v01;
            *(float2*)(cb + (long long)(row + 8) * D_MODEL + col) = v23;
        }
    }
}

// ---------------------------------------------------------------------------
extern "C" void kernel_launch(void* const* d_in, const int* in_sizes, int n_in,
                              void* d_out, int out_size)
{
    const float* q   = (const float*)d_in[0];
    const float* k   = (const float*)d_in[1];
    const float* v   = (const float*)d_in[2];
    const float* w_q = (const float*)d_in[3];
    const float* b_q = (const float*)d_in[4];
    const float* w_k = (const float*)d_in[5];
    const float* b_k = (const float*)d_in[6];
    const float* w_v = (const float*)d_in[7];
    const float* b_v = (const float*)d_in[8];
    const float* w_o = (const float*)d_in[9];
    const float* b_o = (const float*)d_in[10];

    float *gq, *gk, *gv, *gctx, *gattn;
    cudaGetSymbolAddress((void**)&gq,   g_q);
    cudaGetSymbolAddress((void**)&gk,   g_k);
    cudaGetSymbolAddress((void**)&gv,   g_v);
    cudaGetSymbolAddress((void**)&gctx, g_ctx);
    cudaGetSymbolAddress((void**)&gattn, g_attn);

    float* outp = (float*)d_out;
    const long long OUT_ELEMS  = (long long)MROWS * D_MODEL;
    const long long ATTN_ELEMS = (long long)BATCH * NHEAD * SEQ * SEQ;
    float* attn = ((long long)out_size >= OUT_ELEMS + ATTN_ELEMS) ? (outp + OUT_ELEMS)
                                                                  : gattn;

    // --- QKV projections ---
    {
        const dim3 grid(D_MODEL / 64, MROWS / 128, 3);
        qkv_proj_kernel<<<grid, 256>>>(q, k, v, w_q, w_k, w_v, b_q, b_k, b_v,
                                       gq, gk, gv);
    }

    // --- Scores + exp + rowsum ---
    {
        const dim3 grid(SEQ / 128, BATCH * NHEAD);
        scores_kernel<<<grid, 256>>>(gq, gk, attn);
    }

    // --- Normalize (in place) + PV ---
    {
        const dim3 grid(SEQ / 128, BATCH * NHEAD);
        pv_kernel<<<grid, 256>>>(gv, attn, gctx);
    }

    // --- Output projection ---
    {
        const dim3 grid(D_MODEL / 64, MROWS / 128, 1);
        out_proj_kernel<<<grid, 256>>>(gctx, w_o, b_o, outp);
    }
}

// round 6
// speedup vs baseline: 4.7795x; 1.3216x over previous
#include <cuda_runtime.h>
#include <cuda_fp16.h>
#include <math.h>
#include <stdint.h>

// Problem constants
#define D_MODEL 768
#define NHEAD   12
#define DK      64
#define BATCH   2
#define SEQ     2048
#define MROWS   (BATCH*SEQ)   // 4096
#define N1 (MROWS*D_MODEL)    // 3,145,728
#define N2 (D_MODEL*D_MODEL)  // 589,824

// Scratch in device globals (allocation-free rule)
__device__ __half g_xh[3 * N1];    // half copies of q,k,v inputs
__device__ __half g_wh[4 * N2];    // half copies of w_q,w_k,w_v,w_o
__device__ __half g_ph[3 * N1];    // projected qh, kh, vh (half)
__device__ __half g_ctxh[N1];      // attention context (half)
__device__ float  g_inv[BATCH * NHEAD * SEQ];
__device__ float  g_attn[(size_t)BATCH * NHEAD * SEQ * SEQ]; // fallback

// ---------------------------------------------------------------------------
// Low-level helpers
// ---------------------------------------------------------------------------
__device__ __forceinline__ uint32_t packh2(float x, float y) {
    __half2 h = __floats2half2_rn(x, y);
    return *reinterpret_cast<uint32_t*>(&h);
}

__device__ __forceinline__ void mma_f16(float* d, const uint32_t* a, const uint32_t* b) {
    asm volatile(
        "mma.sync.aligned.m16n8k16.row.col.f32.f16.f16.f32 "
        "{%0,%1,%2,%3}, {%4,%5,%6,%7}, {%8,%9}, {%0,%1,%2,%3};\n"
        : "+f"(d[0]), "+f"(d[1]), "+f"(d[2]), "+f"(d[3])
        : "r"(a[0]), "r"(a[1]), "r"(a[2]), "r"(a[3]), "r"(b[0]), "r"(b[1]));
}

__device__ __forceinline__ void ldsm_x4(uint32_t* r, const void* p) {
    uint32_t a = (uint32_t)__cvta_generic_to_shared(p);
    asm volatile("ldmatrix.sync.aligned.m8n8.x4.shared.b16 {%0,%1,%2,%3}, [%4];"
                 : "=r"(r[0]), "=r"(r[1]), "=r"(r[2]), "=r"(r[3]) : "r"(a));
}
__device__ __forceinline__ void ldsm_x4_t(uint32_t* r, const void* p) {
    uint32_t a = (uint32_t)__cvta_generic_to_shared(p);
    asm volatile("ldmatrix.sync.aligned.m8n8.x4.trans.shared.b16 {%0,%1,%2,%3}, [%4];"
                 : "=r"(r[0]), "=r"(r[1]), "=r"(r[2]), "=r"(r[3]) : "r"(a));
}

__device__ __forceinline__ void cp16(void* s, const void* g) {
    uint32_t a = (uint32_t)__cvta_generic_to_shared(s);
    asm volatile("cp.async.cg.shared.global [%0], [%1], 16;" :: "r"(a), "l"(g));
}
__device__ __forceinline__ void cp_commit() {
    asm volatile("cp.async.commit_group;" ::);
}
__device__ __forceinline__ void cp_wait1() {
    asm volatile("cp.async.wait_group 1;" ::);
}
__device__ __forceinline__ void cp_wait0() {
    asm volatile("cp.async.wait_group 0;" ::);
}

// ---------------------------------------------------------------------------
// Convert kernel: fp32 inputs/weights -> half scratch
// ---------------------------------------------------------------------------
__global__ void convert_kernel(const float* __restrict__ q, const float* __restrict__ k,
                               const float* __restrict__ v,
                               const float* __restrict__ wq, const float* __restrict__ wk,
                               const float* __restrict__ wv, const float* __restrict__ wo)
{
    const long long TOT4 = (3LL * N1 + 4LL * N2) / 4;
    for (long long i4 = blockIdx.x * blockDim.x + threadIdx.x; i4 < TOT4;
         i4 += (long long)gridDim.x * blockDim.x) {
        const long long e = i4 * 4;
        const float* src;
        __half* dst;
        if (e < 3LL * N1) {
            const int w = (int)(e / N1);
            const long long off = e - (long long)w * N1;
            src = (w == 0 ? q : w == 1 ? k : v) + off;
            dst = g_xh + e;
        } else {
            const long long e2 = e - 3LL * N1;
            const int w = (int)(e2 / N2);
            const long long off = e2 - (long long)w * N2;
            src = (w == 0 ? wq : w == 1 ? wk : w == 2 ? wv : wo) + off;
            dst = g_wh + e2;
        }
        const float4 f = *(const float4*)src;
        uint2 u;
        u.x = packh2(f.x, f.y);
        u.y = packh2(f.z, f.w);
        *(uint2*)dst = u;
    }
}

// ---------------------------------------------------------------------------
// 768-K GEMM body: C = A_h[4096x768] @ W_h[768x768] + bias
// Block 128x64, BK=32, cp.async double-buffer, ldmatrix fragments.
// 8 warps (4M x 2N), warp tile 32x32.
// ---------------------------------------------------------------------------
template <bool HALF_OUT>
__device__ __forceinline__ void gemm768_body(const __half* __restrict__ A,
                                             const __half* __restrict__ W,
                                             const float* __restrict__ bias,
                                             void* __restrict__ C)
{
    __shared__ alignas(16) __half As[2][128][40];
    __shared__ alignas(16) __half Ws[2][32][72];

    const int tid  = threadIdx.x;
    const int warp = tid >> 5;
    const int lane = tid & 31;
    const int gid  = lane >> 2;
    const int tig  = lane & 3;
    const int wm   = (warp & 3) * 32;
    const int wn   = (warp >> 2) * 32;
    const int lrow = lane & 15;
    const int lcol = (lane >> 4) << 3;

    const int m0 = blockIdx.y * 128;
    const int n0 = blockIdx.x * 64;
    const __half* Ab = A + (long long)m0 * D_MODEL;
    const __half* Wb = W + n0;

    auto issueA = [&](int s, int k0) {
        #pragma unroll
        for (int it = 0; it < 2; it++) {
            const int c = tid + it * 256;        // 0..511
            const int row = c >> 2;              // 0..127
            const int ch  = (c & 3) * 8;         // 0..24
            cp16(&As[s][row][ch], Ab + (long long)row * D_MODEL + k0 + ch);
        }
    };
    auto issueW = [&](int s, int k0) {
        const int row = tid >> 3;                // 0..31
        const int ch  = (tid & 7) * 8;           // 0..56
        cp16(&Ws[s][row][ch], Wb + (long long)(k0 + row) * D_MODEL + ch);
    };

    issueA(0, 0);
    issueW(0, 0);
    cp_commit();

    float acc[2][4][4] = {};

    for (int s = 0; s < 24; s++) {
        if (s < 23) {
            issueA((s + 1) & 1, (s + 1) * 32);
            issueW((s + 1) & 1, (s + 1) * 32);
            cp_commit();
            cp_wait1();
        } else {
            cp_wait0();
        }
        __syncthreads();

        const int bb = s & 1;
        #pragma unroll
        for (int kk = 0; kk < 32; kk += 16) {
            uint32_t af[2][4], bt[2][4];
            ldsm_x4(af[0], &As[bb][wm + lrow][kk + lcol]);
            ldsm_x4(af[1], &As[bb][wm + 16 + lrow][kk + lcol]);
            ldsm_x4_t(bt[0], &Ws[bb][kk + lrow][wn + lcol]);
            ldsm_x4_t(bt[1], &Ws[bb][kk + lrow][wn + 16 + lcol]);
            #pragma unroll
            for (int i = 0; i < 2; i++) {
                mma_f16(acc[i][0], af[i], &bt[0][0]);
                mma_f16(acc[i][1], af[i], &bt[0][2]);
                mma_f16(acc[i][2], af[i], &bt[1][0]);
                mma_f16(acc[i][3], af[i], &bt[1][2]);
            }
        }
        __syncthreads();
    }

    #pragma unroll
    for (int i = 0; i < 2; i++) {
        const int row = m0 + wm + 16 * i + gid;
        #pragma unroll
        for (int j = 0; j < 4; j++) {
            const int col = n0 + wn + 8 * j + 2 * tig;
            const float b0 = bias[col];
            const float b1 = bias[col + 1];
            const float v0 = acc[i][j][0] + b0;
            const float v1 = acc[i][j][1] + b1;
            const float v2 = acc[i][j][2] + b0;
            const float v3 = acc[i][j][3] + b1;
            if (HALF_OUT) {
                __half* Ch = (__half*)C;
                *(uint32_t*)(Ch + (long long)row * D_MODEL + col)       = packh2(v0, v1);
                *(uint32_t*)(Ch + (long long)(row + 8) * D_MODEL + col) = packh2(v2, v3);
            } else {
                float* Cf = (float*)C;
                *(float2*)(Cf + (long long)row * D_MODEL + col)       = make_float2(v0, v1);
                *(float2*)(Cf + (long long)(row + 8) * D_MODEL + col) = make_float2(v2, v3);
            }
        }
    }
}

__global__ __launch_bounds__(256, 3) void qkv_proj_kernel(
    const float* __restrict__ bq, const float* __restrict__ bk, const float* __restrict__ bv)
{
    const int z = blockIdx.z;
    const float* bias = (z == 0) ? bq : (z == 1) ? bk : bv;
    gemm768_body<true>(g_xh + (long long)z * N1, g_wh + (long long)z * N2,
                       bias, g_ph + (long long)z * N1);
}

__global__ __launch_bounds__(256, 3) void out_proj_kernel(
    const float* __restrict__ bo, float* __restrict__ out)
{
    gemm768_body<false>(g_ctxh, g_wh + 3LL * N2, bo, out);
}

// ---------------------------------------------------------------------------
// Scores: per (z, 128-q tile): S = Q K^T / 8, write exp(S) unnormalized,
// accumulate rowsums -> g_inv. K tiles cp.async double-buffered.
// ---------------------------------------------------------------------------
__global__ __launch_bounds__(256, 3) void scores_kernel(float* __restrict__ attn)
{
    __shared__ alignas(16) __half Qs[128][72];
    __shared__ alignas(16) __half Ks[2][64][72];
    __shared__ float rowsum[128];

    const int tid  = threadIdx.x;
    const int warp = tid >> 5;
    const int lane = tid & 31;
    const int gid  = lane >> 2;
    const int tig  = lane & 3;
    const int wm   = (warp & 3) * 32;
    const int wn   = (warp >> 2) * 32;
    const int lrow = lane & 15;
    const int lcol = (lane >> 4) << 3;

    const int q0 = blockIdx.x * 128;
    const int z  = blockIdx.y;
    const int b  = z / NHEAD;
    const int h  = z % NHEAD;

    const __half* qb = g_ph + (long long)b * SEQ * D_MODEL + h * DK;
    const __half* kb = g_ph + N1 + (long long)b * SEQ * D_MODEL + h * DK;
    float* ab = attn + (long long)z * SEQ * SEQ;

    // prologue: Q tile (128x64) + K tile 0 (64x64), one group
    #pragma unroll
    for (int it = 0; it < 4; it++) {
        const int c = tid + it * 256;        // 0..1023
        const int row = c >> 3;
        const int ch  = (c & 7) * 8;
        cp16(&Qs[row][ch], qb + (long long)(q0 + row) * D_MODEL + ch);
    }
    #pragma unroll
    for (int it = 0; it < 2; it++) {
        const int c = tid + it * 256;        // 0..511
        const int key = c >> 3;
        const int ch  = (c & 7) * 8;
        cp16(&Ks[0][key][ch], kb + (long long)key * D_MODEL + ch);
    }
    cp_commit();
    if (tid < 128) rowsum[tid] = 0.f;

    for (int t = 0; t < 32; t++) {
        if (t < 31) {
            const int nn = (t + 1) * 64;
            #pragma unroll
            for (int it = 0; it < 2; it++) {
                const int c = tid + it * 256;
                const int key = c >> 3;
                const int ch  = (c & 7) * 8;
                cp16(&Ks[(t + 1) & 1][key][ch], kb + (long long)(nn + key) * D_MODEL + ch);
            }
            cp_commit();
            cp_wait1();
        } else {
            cp_wait0();
        }
        __syncthreads();

        const int bb = t & 1;
        const int n0 = t * 64;

        float acc[2][4][4] = {};
        #pragma unroll
        for (int kk = 0; kk < 64; kk += 16) {
            uint32_t af[2][4], kf[2][4];
            ldsm_x4(af[0], &Qs[wm + lrow][kk + lcol]);
            ldsm_x4(af[1], &Qs[wm + 16 + lrow][kk + lcol]);
            ldsm_x4(kf[0], &Ks[bb][wn + lrow][kk + lcol]);
            ldsm_x4(kf[1], &Ks[bb][wn + 16 + lrow][kk + lcol]);
            // plain-ldsm on [n][k]: frag j pairing {r0,r2}, {r1,r3}
            uint32_t b0[2] = { kf[0][0], kf[0][2] };
            uint32_t b1[2] = { kf[0][1], kf[0][3] };
            uint32_t b2[2] = { kf[1][0], kf[1][2] };
            uint32_t b3[2] = { kf[1][1], kf[1][3] };
            #pragma unroll
            for (int i = 0; i < 2; i++) {
                mma_f16(acc[i][0], af[i], b0);
                mma_f16(acc[i][1], af[i], b1);
                mma_f16(acc[i][2], af[i], b2);
                mma_f16(acc[i][3], af[i], b3);
            }
        }

        // exp epilogue: unnormalized exp -> attn, rowsum accumulate
        #pragma unroll
        for (int i = 0; i < 2; i++) {
            const int r = wm + 16 * i + gid;
            float s0 = 0.f, s1 = 0.f;
            #pragma unroll
            for (int j = 0; j < 4; j++) {
                const int col = n0 + wn + 8 * j + 2 * tig;
                float2 e01, e23;
                e01.x = __expf(acc[i][j][0] * 0.125f);
                e01.y = __expf(acc[i][j][1] * 0.125f);
                e23.x = __expf(acc[i][j][2] * 0.125f);
                e23.y = __expf(acc[i][j][3] * 0.125f);
                *(float2*)(ab + (long long)(q0 + r) * SEQ + col)     = e01;
                *(float2*)(ab + (long long)(q0 + r + 8) * SEQ + col) = e23;
                s0 += e01.x + e01.y;
                s1 += e23.x + e23.y;
            }
            s0 += __shfl_xor_sync(0xffffffffu, s0, 1);
            s0 += __shfl_xor_sync(0xffffffffu, s0, 2);
            s1 += __shfl_xor_sync(0xffffffffu, s1, 1);
            s1 += __shfl_xor_sync(0xffffffffu, s1, 2);
            if (tig == 0) {
                atomicAdd(&rowsum[r], s0);
                atomicAdd(&rowsum[r + 8], s1);
            }
        }
        __syncthreads();
    }

    if (tid < 128) g_inv[(long long)z * SEQ + q0 + tid] = 1.0f / rowsum[tid];
}

// ---------------------------------------------------------------------------
// PV: per (z, 128-q tile): normalize attn in place, ctx = P @ V (half out).
// V tiles cp.async double-buffered; P staged to smem as half.
// ---------------------------------------------------------------------------
__global__ __launch_bounds__(256, 3) void pv_kernel(float* __restrict__ attn)
{
    __shared__ alignas(16) __half Ps[128][72];
    __shared__ alignas(16) __half Vs[2][64][72];
    __shared__ float invs[128];

    const int tid  = threadIdx.x;
    const int warp = tid >> 5;
    const int lane = tid & 31;
    const int gid  = lane >> 2;
    const int tig  = lane & 3;
    const int wm   = (warp & 3) * 32;
    const int wn   = (warp >> 2) * 32;
    const int lrow = lane & 15;
    const int lcol = (lane >> 4) << 3;

    const int q0 = blockIdx.x * 128;
    const int z  = blockIdx.y;
    const int b  = z / NHEAD;
    const int h  = z % NHEAD;

    const __half* vb = g_ph + 2LL * N1 + (long long)b * SEQ * D_MODEL + h * DK;
    float* ab = attn + (long long)z * SEQ * SEQ;
    __half* cb = g_ctxh + (long long)b * SEQ * D_MODEL + h * DK;

    if (tid < 128) invs[tid] = g_inv[(long long)z * SEQ + q0 + tid];

    // prologue: V tile 0
    #pragma unroll
    for (int it = 0; it < 2; it++) {
        const int c = tid + it * 256;
        const int key = c >> 3;
        const int ch  = (c & 7) * 8;
        cp16(&Vs[0][key][ch], vb + (long long)key * D_MODEL + ch);
    }
    cp_commit();
    __syncthreads();   // invs visible

    float cacc[2][4][4] = {};

    for (int t = 0; t < 32; t++) {
        const int n0 = t * 64;
        if (t < 31) {
            const int nn = (t + 1) * 64;
            #pragma unroll
            for (int it = 0; it < 2; it++) {
                const int c = tid + it * 256;
                const int key = c >> 3;
                const int ch  = (c & 7) * 8;
                cp16(&Vs[(t + 1) & 1][key][ch], vb + (long long)(nn + key) * D_MODEL + ch);
            }
            cp_commit();
        }

        // normalize P tile in place + stage half into Ps
        #pragma unroll
        for (int it = 0; it < 8; it++) {
            const int idx = tid + it * 256;     // 0..2047
            const int row = idx >> 4;
            const int c4  = (idx & 15) * 4;
            float* p = ab + (long long)(q0 + row) * SEQ + n0 + c4;
            float4 v = *(const float4*)p;
            const float inv = invs[row];
            v.x *= inv; v.y *= inv; v.z *= inv; v.w *= inv;
            *(float4*)p = v;
            *(uint32_t*)&Ps[row][c4]     = packh2(v.x, v.y);
            *(uint32_t*)&Ps[row][c4 + 2] = packh2(v.z, v.w);
        }

        if (t < 31) cp_wait1(); else cp_wait0();
        __syncthreads();

        const int bb = t & 1;
        #pragma unroll
        for (int kk = 0; kk < 64; kk += 16) {
            uint32_t af[2][4], vt[2][4];
            ldsm_x4(af[0], &Ps[wm + lrow][kk + lcol]);
            ldsm_x4(af[1], &Ps[wm + 16 + lrow][kk + lcol]);
            ldsm_x4_t(vt[0], &Vs[bb][kk + lrow][wn + lcol]);
            ldsm_x4_t(vt[1], &Vs[bb][kk + lrow][wn + 16 + lcol]);
            #pragma unroll
            for (int i = 0; i < 2; i++) {
                mma_f16(cacc[i][0], af[i], &vt[0][0]);
                mma_f16(cacc[i][1], af[i], &vt[0][2]);
                mma_f16(cacc[i][2], af[i], &vt[1][0]);
                mma_f16(cacc[i][3], af[i], &vt[1][2]);
            }
        }
        __syncthreads();
    }

    // ctx epilogue (half)
    #pragma unroll
    for (int i = 0; i < 2; i++) {
        const int row = q0 + wm + 16 * i + gid;
        #pragma unroll
        for (int j = 0; j < 4; j++) {
            const int col = wn + 8 * j + 2 * tig;
            *(uint32_t*)(cb + (long long)row * D_MODEL + col)       = packh2(cacc[i][j][0], cacc[i][j][1]);
            *(uint32_t*)(cb + (long long)(row + 8) * D_MODEL + col) = packh2(cacc[i][j][2], cacc[i][j][3]);
        }
    }
}

// ---------------------------------------------------------------------------
extern "C" void kernel_launch(void* const* d_in, const int* in_sizes, int n_in,
                              void* d_out, int out_size)
{
    const float* q   = (const float*)d_in[0];
    const float* k   = (const float*)d_in[1];
    const float* v   = (const float*)d_in[2];
    const float* w_q = (const float*)d_in[3];
    const float* b_q = (const float*)d_in[4];
    const float* w_k = (const float*)d_in[5];
    const float* b_k = (const float*)d_in[6];
    const float* w_v = (const float*)d_in[7];
    const float* b_v = (const float*)d_in[8];
    const float* w_o = (const float*)d_in[9];
    const float* b_o = (const float*)d_in[10];

    float* gattn;
    cudaGetSymbolAddress((void**)&gattn, g_attn);

    float* outp = (float*)d_out;
    const long long OUT_ELEMS  = (long long)MROWS * D_MODEL;
    const long long ATTN_ELEMS = (long long)BATCH * NHEAD * SEQ * SEQ;
    float* attn = ((long long)out_size >= OUT_ELEMS + ATTN_ELEMS) ? (outp + OUT_ELEMS)
                                                                  : gattn;

    // 0. convert inputs + weights to half
    convert_kernel<<<1024, 256>>>(q, k, v, w_q, w_k, w_v, w_o);

    // 1. QKV projections (half in, half out)
    {
        const dim3 grid(D_MODEL / 64, MROWS / 128, 3);
        qkv_proj_kernel<<<grid, 256>>>(b_q, b_k, b_v);
    }

    // 2. scores + exp + rowsum
    {
        const dim3 grid(SEQ / 128, BATCH * NHEAD);
        scores_kernel<<<grid, 256>>>(attn);
    }

    // 3. normalize (in place) + PV
    {
        const dim3 grid(SEQ / 128, BATCH * NHEAD);
        pv_kernel<<<grid, 256>>>(attn);
    }

    // 4. output projection (fp32 out)
    {
        const dim3 grid(D_MODEL / 64, MROWS / 128, 1);
        out_proj_kernel<<<grid, 256>>>(b_o, outp);
    }
}

// round 7
// speedup vs baseline: 6.2504x; 1.3078x over previous
#include <cuda_runtime.h>
#include <cuda_fp16.h>
#include <math.h>
#include <stdint.h>

// Problem constants
#define D_MODEL 768
#define NHEAD   12
#define DK      64
#define BATCH   2
#define SEQ     2048
#define MROWS   (BATCH*SEQ)   // 4096
#define N1 (MROWS*D_MODEL)    // 3,145,728
#define N2 (D_MODEL*D_MODEL)  // 589,824

// Scratch in device globals (allocation-free rule)
__device__ __half g_xh[3 * N1];    // half copies of q,k,v inputs
__device__ __half g_wh[4 * N2];    // half copies of w_q,w_k,w_v,w_o
__device__ __half g_ph[3 * N1];    // projected qh, kh, vh (half)
__device__ __half g_ctxh[N1];      // attention context (half)
__device__ float  g_attn[(size_t)BATCH * NHEAD * SEQ * SEQ]; // fallback

// ---------------------------------------------------------------------------
// Low-level helpers
// ---------------------------------------------------------------------------
__device__ __forceinline__ uint32_t packh2(float x, float y) {
    __half2 h = __floats2half2_rn(x, y);
    return *reinterpret_cast<uint32_t*>(&h);
}

__device__ __forceinline__ void mma_f16(float* d, const uint32_t* a, const uint32_t* b) {
    asm volatile(
        "mma.sync.aligned.m16n8k16.row.col.f32.f16.f16.f32 "
        "{%0,%1,%2,%3}, {%4,%5,%6,%7}, {%8,%9}, {%0,%1,%2,%3};\n"
        : "+f"(d[0]), "+f"(d[1]), "+f"(d[2]), "+f"(d[3])
        : "r"(a[0]), "r"(a[1]), "r"(a[2]), "r"(a[3]), "r"(b[0]), "r"(b[1]));
}

__device__ __forceinline__ void ldsm_x4(uint32_t* r, const void* p) {
    uint32_t a = (uint32_t)__cvta_generic_to_shared(p);
    asm volatile("ldmatrix.sync.aligned.m8n8.x4.shared.b16 {%0,%1,%2,%3}, [%4];"
                 : "=r"(r[0]), "=r"(r[1]), "=r"(r[2]), "=r"(r[3]) : "r"(a));
}
__device__ __forceinline__ void ldsm_x4_t(uint32_t* r, const void* p) {
    uint32_t a = (uint32_t)__cvta_generic_to_shared(p);
    asm volatile("ldmatrix.sync.aligned.m8n8.x4.trans.shared.b16 {%0,%1,%2,%3}, [%4];"
                 : "=r"(r[0]), "=r"(r[1]), "=r"(r[2]), "=r"(r[3]) : "r"(a));
}

__device__ __forceinline__ void cp16(void* s, const void* g) {
    uint32_t a = (uint32_t)__cvta_generic_to_shared(s);
    asm volatile("cp.async.cg.shared.global [%0], [%1], 16;" :: "r"(a), "l"(g));
}
__device__ __forceinline__ void cp_commit() {
    asm volatile("cp.async.commit_group;" ::);
}
__device__ __forceinline__ void cp_wait1() {
    asm volatile("cp.async.wait_group 1;" ::);
}
__device__ __forceinline__ void cp_wait0() {
    asm volatile("cp.async.wait_group 0;" ::);
}

// ---------------------------------------------------------------------------
// Convert kernel: fp32 inputs/weights -> half scratch
// ---------------------------------------------------------------------------
__global__ void convert_kernel(const float* __restrict__ q, const float* __restrict__ k,
                               const float* __restrict__ v,
                               const float* __restrict__ wq, const float* __restrict__ wk,
                               const float* __restrict__ wv, const float* __restrict__ wo)
{
    const long long TOT4 = (3LL * N1 + 4LL * N2) / 4;
    for (long long i4 = blockIdx.x * blockDim.x + threadIdx.x; i4 < TOT4;
         i4 += (long long)gridDim.x * blockDim.x) {
        const long long e = i4 * 4;
        const float* src;
        __half* dst;
        if (e < 3LL * N1) {
            const int w = (int)(e / N1);
            const long long off = e - (long long)w * N1;
            src = (w == 0 ? q : w == 1 ? k : v) + off;
            dst = g_xh + e;
        } else {
            const long long e2 = e - 3LL * N1;
            const int w = (int)(e2 / N2);
            const long long off = e2 - (long long)w * N2;
            src = (w == 0 ? wq : w == 1 ? wk : w == 2 ? wv : wo) + off;
            dst = g_wh + e2;
        }
        const float4 f = *(const float4*)src;
        uint2 u;
        u.x = packh2(f.x, f.y);
        u.y = packh2(f.z, f.w);
        *(uint2*)dst = u;
    }
}

// ---------------------------------------------------------------------------
// 768-K GEMM body: C = A_h[4096x768] @ W_h[768x768] + bias
// Block 128x64, BK=32, cp.async double-buffer, ldmatrix fragments.
// ---------------------------------------------------------------------------
template <bool HALF_OUT>
__device__ __forceinline__ void gemm768_body(const __half* __restrict__ A,
                                             const __half* __restrict__ W,
                                             const float* __restrict__ bias,
                                             void* __restrict__ C)
{
    __shared__ alignas(16) __half As[2][128][40];
    __shared__ alignas(16) __half Ws[2][32][72];

    const int tid  = threadIdx.x;
    const int warp = tid >> 5;
    const int lane = tid & 31;
    const int gid  = lane >> 2;
    const int tig  = lane & 3;
    const int wm   = (warp & 3) * 32;
    const int wn   = (warp >> 2) * 32;
    const int lrow = lane & 15;
    const int lcol = (lane >> 4) << 3;

    const int m0 = blockIdx.y * 128;
    const int n0 = blockIdx.x * 64;
    const __half* Ab = A + (long long)m0 * D_MODEL;
    const __half* Wb = W + n0;

    auto issueA = [&](int s, int k0) {
        #pragma unroll
        for (int it = 0; it < 2; it++) {
            const int c = tid + it * 256;
            const int row = c >> 2;
            const int ch  = (c & 3) * 8;
            cp16(&As[s][row][ch], Ab + (long long)row * D_MODEL + k0 + ch);
        }
    };
    auto issueW = [&](int s, int k0) {
        const int row = tid >> 3;
        const int ch  = (tid & 7) * 8;
        cp16(&Ws[s][row][ch], Wb + (long long)(k0 + row) * D_MODEL + ch);
    };

    issueA(0, 0);
    issueW(0, 0);
    cp_commit();

    float acc[2][4][4] = {};

    for (int s = 0; s < 24; s++) {
        if (s < 23) {
            issueA((s + 1) & 1, (s + 1) * 32);
            issueW((s + 1) & 1, (s + 1) * 32);
            cp_commit();
            cp_wait1();
        } else {
            cp_wait0();
        }
        __syncthreads();

        const int bb = s & 1;
        #pragma unroll
        for (int kk = 0; kk < 32; kk += 16) {
            uint32_t af[2][4], bt[2][4];
            ldsm_x4(af[0], &As[bb][wm + lrow][kk + lcol]);
            ldsm_x4(af[1], &As[bb][wm + 16 + lrow][kk + lcol]);
            ldsm_x4_t(bt[0], &Ws[bb][kk + lrow][wn + lcol]);
            ldsm_x4_t(bt[1], &Ws[bb][kk + lrow][wn + 16 + lcol]);
            #pragma unroll
            for (int i = 0; i < 2; i++) {
                mma_f16(acc[i][0], af[i], &bt[0][0]);
                mma_f16(acc[i][1], af[i], &bt[0][2]);
                mma_f16(acc[i][2], af[i], &bt[1][0]);
                mma_f16(acc[i][3], af[i], &bt[1][2]);
            }
        }
        __syncthreads();
    }

    #pragma unroll
    for (int i = 0; i < 2; i++) {
        const int row = m0 + wm + 16 * i + gid;
        #pragma unroll
        for (int j = 0; j < 4; j++) {
            const int col = n0 + wn + 8 * j + 2 * tig;
            const float b0 = bias[col];
            const float b1 = bias[col + 1];
            const float v0 = acc[i][j][0] + b0;
            const float v1 = acc[i][j][1] + b1;
            const float v2 = acc[i][j][2] + b0;
            const float v3 = acc[i][j][3] + b1;
            if (HALF_OUT) {
                __half* Ch = (__half*)C;
                *(uint32_t*)(Ch + (long long)row * D_MODEL + col)       = packh2(v0, v1);
                *(uint32_t*)(Ch + (long long)(row + 8) * D_MODEL + col) = packh2(v2, v3);
            } else {
                float* Cf = (float*)C;
                *(float2*)(Cf + (long long)row * D_MODEL + col)       = make_float2(v0, v1);
                *(float2*)(Cf + (long long)(row + 8) * D_MODEL + col) = make_float2(v2, v3);
            }
        }
    }
}

__global__ __launch_bounds__(256, 3) void qkv_proj_kernel(
    const float* __restrict__ bq, const float* __restrict__ bk, const float* __restrict__ bv)
{
    const int z = blockIdx.z;
    const float* bias = (z == 0) ? bq : (z == 1) ? bk : bv;
    gemm768_body<true>(g_xh + (long long)z * N1, g_wh + (long long)z * N2,
                       bias, g_ph + (long long)z * N1);
}

__global__ __launch_bounds__(256, 3) void out_proj_kernel(
    const float* __restrict__ bo, float* __restrict__ out)
{
    gemm768_body<false>(g_ctxh, g_wh + 3LL * N2, bo, out);
}

// ---------------------------------------------------------------------------
// Fused attention: per (z, 128-q tile)
//   pass 1: S = Q K^T (fp16 MMA), rowsum of exp(S/8)  — no gmem writes
//   pass 2: recompute S, p = exp(S/8)*inv, write p to attn (only touch),
//           stash half(p) in smem, ctx += p @ V
// ---------------------------------------------------------------------------
struct SmemAttn {
    __half Qs[128][72];      // 18 KB, persists both passes
    __half Ks[2][64][72];    // 18 KB double-buffered
    __half Vs[2][64][72];    // 18 KB double-buffered (pass 2 only)
    __half Ps[128][72];      // 18 KB normalized p (pass 2)
    float  rowsum[128];
};

__global__ __launch_bounds__(256, 2) void fused_attn_kernel(float* __restrict__ attn)
{
    extern __shared__ char smraw[];
    SmemAttn& sm = *reinterpret_cast<SmemAttn*>(smraw);

    const int tid  = threadIdx.x;
    const int warp = tid >> 5;
    const int lane = tid & 31;
    const int gid  = lane >> 2;
    const int tig  = lane & 3;
    const int wm   = (warp & 3) * 32;
    const int wn   = (warp >> 2) * 32;
    const int lrow = lane & 15;
    const int lcol = (lane >> 4) << 3;

    const int q0 = blockIdx.x * 128;
    const int z  = blockIdx.y;
    const int b  = z / NHEAD;
    const int h  = z % NHEAD;

    const __half* qb = g_ph + (long long)b * SEQ * D_MODEL + h * DK;
    const __half* kb = g_ph + N1 + (long long)b * SEQ * D_MODEL + h * DK;
    const __half* vb = g_ph + 2LL * N1 + (long long)b * SEQ * D_MODEL + h * DK;
    float* ab = attn + (long long)z * SEQ * SEQ;
    __half* cb = g_ctxh + (long long)b * SEQ * D_MODEL + h * DK;

    auto issueK = [&](int s, int n0) {
        #pragma unroll
        for (int it = 0; it < 2; it++) {
            const int c = tid + it * 256;
            const int key = c >> 3;
            const int ch  = (c & 7) * 8;
            cp16(&sm.Ks[s][key][ch], kb + (long long)(n0 + key) * D_MODEL + ch);
        }
    };
    auto issueV = [&](int s, int n0) {
        #pragma unroll
        for (int it = 0; it < 2; it++) {
            const int c = tid + it * 256;
            const int key = c >> 3;
            const int ch  = (c & 7) * 8;
            cp16(&sm.Vs[s][key][ch], vb + (long long)(n0 + key) * D_MODEL + ch);
        }
    };

    // prologue: Q tile + K tile 0
    #pragma unroll
    for (int it = 0; it < 4; it++) {
        const int c = tid + it * 256;
        const int row = c >> 3;
        const int ch  = (c & 7) * 8;
        cp16(&sm.Qs[row][ch], qb + (long long)(q0 + row) * D_MODEL + ch);
    }
    issueK(0, 0);
    cp_commit();
    if (tid < 128) sm.rowsum[tid] = 0.f;

    // =========================== PASS 1: rowsums ===========================
    for (int t = 0; t < 32; t++) {
        if (t < 31) {
            issueK((t + 1) & 1, (t + 1) * 64);
            cp_commit();
            cp_wait1();
        } else {
            cp_wait0();
        }
        __syncthreads();

        const int bb = t & 1;
        float sacc[2][4][4] = {};
        #pragma unroll
        for (int kk = 0; kk < 64; kk += 16) {
            uint32_t af[2][4], kf[2][4];
            ldsm_x4(af[0], &sm.Qs[wm + lrow][kk + lcol]);
            ldsm_x4(af[1], &sm.Qs[wm + 16 + lrow][kk + lcol]);
            ldsm_x4(kf[0], &sm.Ks[bb][wn + lrow][kk + lcol]);
            ldsm_x4(kf[1], &sm.Ks[bb][wn + 16 + lrow][kk + lcol]);
            uint32_t b0[2] = { kf[0][0], kf[0][2] };
            uint32_t b1[2] = { kf[0][1], kf[0][3] };
            uint32_t b2[2] = { kf[1][0], kf[1][2] };
            uint32_t b3[2] = { kf[1][1], kf[1][3] };
            #pragma unroll
            for (int i = 0; i < 2; i++) {
                mma_f16(sacc[i][0], af[i], b0);
                mma_f16(sacc[i][1], af[i], b1);
                mma_f16(sacc[i][2], af[i], b2);
                mma_f16(sacc[i][3], af[i], b3);
            }
        }

        #pragma unroll
        for (int i = 0; i < 2; i++) {
            const int r = wm + 16 * i + gid;
            float s0 = 0.f, s1 = 0.f;
            #pragma unroll
            for (int j = 0; j < 4; j++) {
                s0 += __expf(sacc[i][j][0] * 0.125f) + __expf(sacc[i][j][1] * 0.125f);
                s1 += __expf(sacc[i][j][2] * 0.125f) + __expf(sacc[i][j][3] * 0.125f);
            }
            s0 += __shfl_xor_sync(0xffffffffu, s0, 1);
            s0 += __shfl_xor_sync(0xffffffffu, s0, 2);
            s1 += __shfl_xor_sync(0xffffffffu, s1, 1);
            s1 += __shfl_xor_sync(0xffffffffu, s1, 2);
            if (tig == 0) {
                atomicAdd(&sm.rowsum[r], s0);
                atomicAdd(&sm.rowsum[r + 8], s1);
            }
        }
        __syncthreads();
    }

    if (tid < 128) sm.rowsum[tid] = 1.0f / sm.rowsum[tid];
    __syncthreads();

    // hoist per-thread inverse rowsums
    float invr[2][2];
    #pragma unroll
    for (int i = 0; i < 2; i++) {
        invr[i][0] = sm.rowsum[wm + 16 * i + gid];
        invr[i][1] = sm.rowsum[wm + 16 * i + gid + 8];
    }

    // ================= PASS 2: recompute, write p, accumulate PV ===========
    issueK(0, 0);
    issueV(0, 0);
    cp_commit();

    float cacc[2][4][4] = {};

    for (int t = 0; t < 32; t++) {
        const int n0 = t * 64;
        if (t < 31) {
            issueK((t + 1) & 1, (t + 1) * 64);
            issueV((t + 1) & 1, (t + 1) * 64);
            cp_commit();
            cp_wait1();
        } else {
            cp_wait0();
        }
        __syncthreads();   // loads visible; prev iteration's PV done (Ps free)

        const int bb = t & 1;

        // scores recompute
        float sacc[2][4][4] = {};
        #pragma unroll
        for (int kk = 0; kk < 64; kk += 16) {
            uint32_t af[2][4], kf[2][4];
            ldsm_x4(af[0], &sm.Qs[wm + lrow][kk + lcol]);
            ldsm_x4(af[1], &sm.Qs[wm + 16 + lrow][kk + lcol]);
            ldsm_x4(kf[0], &sm.Ks[bb][wn + lrow][kk + lcol]);
            ldsm_x4(kf[1], &sm.Ks[bb][wn + 16 + lrow][kk + lcol]);
            uint32_t b0[2] = { kf[0][0], kf[0][2] };
            uint32_t b1[2] = { kf[0][1], kf[0][3] };
            uint32_t b2[2] = { kf[1][0], kf[1][2] };
            uint32_t b3[2] = { kf[1][1], kf[1][3] };
            #pragma unroll
            for (int i = 0; i < 2; i++) {
                mma_f16(sacc[i][0], af[i], b0);
                mma_f16(sacc[i][1], af[i], b1);
                mma_f16(sacc[i][2], af[i], b2);
                mma_f16(sacc[i][3], af[i], b3);
            }
        }

        // normalized p: write to attn (only gmem touch) + stash half in Ps
        #pragma unroll
        for (int i = 0; i < 2; i++) {
            const int r = wm + 16 * i + gid;
            const float inv0 = invr[i][0];
            const float inv1 = invr[i][1];
            #pragma unroll
            for (int j = 0; j < 4; j++) {
                const int cl = wn + 8 * j + 2 * tig;
                float2 e01, e23;
                e01.x = __expf(sacc[i][j][0] * 0.125f) * inv0;
                e01.y = __expf(sacc[i][j][1] * 0.125f) * inv0;
                e23.x = __expf(sacc[i][j][2] * 0.125f) * inv1;
                e23.y = __expf(sacc[i][j][3] * 0.125f) * inv1;
                *(float2*)(ab + (long long)(q0 + r) * SEQ + n0 + cl)     = e01;
                *(float2*)(ab + (long long)(q0 + r + 8) * SEQ + n0 + cl) = e23;
                *(uint32_t*)&sm.Ps[r][cl]     = packh2(e01.x, e01.y);
                *(uint32_t*)&sm.Ps[r + 8][cl] = packh2(e23.x, e23.y);
            }
        }
        __syncthreads();   // Ps visible to all warps

        // PV MMA: ctx += P @ V
        #pragma unroll
        for (int kk = 0; kk < 64; kk += 16) {
            uint32_t af[2][4], vt[2][4];
            ldsm_x4(af[0], &sm.Ps[wm + lrow][kk + lcol]);
            ldsm_x4(af[1], &sm.Ps[wm + 16 + lrow][kk + lcol]);
            ldsm_x4_t(vt[0], &sm.Vs[bb][kk + lrow][wn + lcol]);
            ldsm_x4_t(vt[1], &sm.Vs[bb][kk + lrow][wn + 16 + lcol]);
            #pragma unroll
            for (int i = 0; i < 2; i++) {
                mma_f16(cacc[i][0], af[i], &vt[0][0]);
                mma_f16(cacc[i][1], af[i], &vt[0][2]);
                mma_f16(cacc[i][2], af[i], &vt[1][0]);
                mma_f16(cacc[i][3], af[i], &vt[1][2]);
            }
        }
        __syncthreads();   // Ks/Vs[bb] free for next iteration's prefetch
    }

    // ctx epilogue (half)
    #pragma unroll
    for (int i = 0; i < 2; i++) {
        const int row = q0 + wm + 16 * i + gid;
        #pragma unroll
        for (int j = 0; j < 4; j++) {
            const int col = wn + 8 * j + 2 * tig;
            *(uint32_t*)(cb + (long long)row * D_MODEL + col)       = packh2(cacc[i][j][0], cacc[i][j][1]);
            *(uint32_t*)(cb + (long long)(row + 8) * D_MODEL + col) = packh2(cacc[i][j][2], cacc[i][j][3]);
        }
    }
}

// ---------------------------------------------------------------------------
extern "C" void kernel_launch(void* const* d_in, const int* in_sizes, int n_in,
                              void* d_out, int out_size)
{
    const float* q   = (const float*)d_in[0];
    const float* k   = (const float*)d_in[1];
    const float* v   = (const float*)d_in[2];
    const float* w_q = (const float*)d_in[3];
    const float* b_q = (const float*)d_in[4];
    const float* b_k = (const float*)d_in[6];
    const float* w_k = (const float*)d_in[5];
    const float* w_v = (const float*)d_in[7];
    const float* b_v = (const float*)d_in[8];
    const float* w_o = (const float*)d_in[9];
    const float* b_o = (const float*)d_in[10];

    float* gattn;
    cudaGetSymbolAddress((void**)&gattn, g_attn);

    float* outp = (float*)d_out;
    const long long OUT_ELEMS  = (long long)MROWS * D_MODEL;
    const long long ATTN_ELEMS = (long long)BATCH * NHEAD * SEQ * SEQ;
    float* attn = ((long long)out_size >= OUT_ELEMS + ATTN_ELEMS) ? (outp + OUT_ELEMS)
                                                                  : gattn;

    // 0. convert inputs + weights to half
    convert_kernel<<<1024, 256>>>(q, k, v, w_q, w_k, w_v, w_o);

    // 1. QKV projections (half in, half out)
    {
        const dim3 grid(D_MODEL / 64, MROWS / 128, 3);
        qkv_proj_kernel<<<grid, 256>>>(b_q, b_k, b_v);
    }

    // 2. fused attention (scores + softmax + attn write + PV)
    {
        static int smem_set = 0;
        const int smem_bytes = (int)sizeof(SmemAttn);
        if (!smem_set) {
            cudaFuncSetAttribute(fused_attn_kernel,
                                 cudaFuncAttributeMaxDynamicSharedMemorySize, smem_bytes);
            smem_set = 1;
        }
        const dim3 grid(SEQ / 128, BATCH * NHEAD);
        fused_attn_kernel<<<grid, 256, smem_bytes>>>(attn);
    }

    // 3. output projection (fp32 out)
    {
        const dim3 grid(D_MODEL / 64, MROWS / 128, 1);
        out_proj_kernel<<<grid, 256>>>(b_o, outp);
    }
}